// round 9
// baseline (speedup 1.0000x reference)
#include <cuda_runtime.h>
#include <cuda_bf16.h>
#include <math.h>

#define Bsz 32
#define Csz 129
#define Tsz 1000
#define Dsz 256
#define Nst 64
#define NL  4
#define FFTN 2048

// ---------------- scratch (device globals; no runtime alloc) ----------------
__device__ float  d_h [Bsz*Tsz*Dsz];     // hidden state (B,T,D)
__device__ float  d_xt[Bsz*Tsz*Dsz];     // raw projection (B,T,D)
__device__ float  d_xt2[Bsz*Tsz*Dsz];    // normalized transposed (B,D,T); conv in-place
__device__ float  d_k [NL*Dsz*Tsz];      // S4 kernels
__device__ float2 d_kf[NL*Dsz*FFTN];     // spectra of kernels
__device__ float  d_Ad[NL*Nst*Nst];
__device__ float  d_twr[256];
__device__ float  d_twi[256];
__device__ float  d_wt[Csz*Dsz];         // transposed w_in
__device__ float  d_pe[Tsz*Dsz];         // positional encoding table

#define PI_D 3.14159265358979323846

// ---------------- complex helpers ----------------
struct C2 { float x, y; };
__device__ __forceinline__ C2 cmul(C2 a, C2 b){ C2 r; r.x = a.x*b.x - a.y*b.y; r.y = a.x*b.y + a.y*b.x; return r; }
__device__ __forceinline__ C2 cadd(C2 a, C2 b){ C2 r; r.x = a.x+b.x; r.y = a.y+b.y; return r; }
__device__ __forceinline__ C2 csub(C2 a, C2 b){ C2 r; r.x = a.x-b.x; r.y = a.y-b.y; return r; }
__device__ __forceinline__ C2 cmulni(C2 a){ C2 r; r.x = a.y; r.y = -a.x; return r; }  // a * (-i)

#define PD(i) ((i) + ((i)>>5))

// ---------------- f32x2 packed fma ----------------
__device__ __forceinline__ unsigned long long fma2(unsigned long long a, unsigned long long b, unsigned long long c){
    unsigned long long d;
    asm("fma.rn.f32x2 %0, %1, %2, %3;" : "=l"(d) : "l"(a), "l"(b), "l"(c));
    return d;
}
__device__ __forceinline__ float2 unpack2(unsigned long long v){
    float2 r; asm("mov.b64 {%0, %1}, %2;" : "=f"(r.x), "=f"(r.y) : "l"(v)); return r;
}

// ---------------- setup: twiddles, w transpose, pos-encoding ----------------
__global__ void setup_kernel(const float* __restrict__ w_in) {
    int idx = blockIdx.x * blockDim.x + threadIdx.x;
    int stride = gridDim.x * blockDim.x;
    if (idx < 256) {
        double ang = -2.0 * PI_D * (double)idx / (double)FFTN;
        d_twr[idx] = (float)cos(ang);
        d_twi[idx] = (float)sin(ang);
    }
    for (int i = idx; i < Csz*Dsz; i += stride) {
        int dd = i / Csz, c = i % Csz;
        d_wt[c*Dsz + dd] = w_in[i];
    }
    for (int i = idx; i < Tsz*Dsz; i += stride) {
        int t = i / Dsz, dd = i % Dsz;
        double divv = exp(-(double)(dd >> 1) * 2.0 * log(10000.0) / (double)Dsz);
        double arg = (double)t * divv;
        d_pe[i] = (float)((dd & 1) ? cos(arg) : sin(arg));
    }
}

// ---------------- Ad = solve(I - dtA, I + dtA): pivot-free Gauss-Jordan -----
__global__ void compute_Ad_kernel(const float* __restrict__ s4_logdt) {
    int layer = blockIdx.x;
    __shared__ float M[64][65];
    __shared__ float R[64][65];
    __shared__ float fcol[64];
    __shared__ float rkM[64];
    __shared__ float rkR[64];
    int tid = threadIdx.x; // 512 threads

    float logdt = s4_logdt[layer*Dsz + 0];
    float dt = fminf(fmaxf(expf(logdt), 1e-4f), 0.1f);
    float hdt = dt * 0.5f;

    for (int idx = tid; idx < 64*64; idx += 512) {
        int i = idx >> 6, j = idx & 63;
        float Pi = sqrtf(1.0f + 2.0f*i), Pj = sqrtf(1.0f + 2.0f*j);
        float a;
        if (i == j)      a = -((float)i + 0.5f);
        else if (i > j)  a = -Pi*Pj;
        else             a =  Pi*Pj;
        float eye = (i == j) ? 1.0f : 0.0f;
        M[i][j] = eye - hdt*a;
        R[i][j] = eye + hdt*a;
    }
    __syncthreads();

    for (int k = 0; k < 64; k++) {
        float ipv = 1.0f / M[k][k];
        if (tid < 64) {
            fcol[tid] = (tid == k) ? 0.0f : M[tid][k] * ipv;
        } else if (tid < 128) {
            int c = tid - 64; rkM[c] = M[k][c];
        } else if (tid < 192) {
            int c = tid - 128; rkR[c] = R[k][c];
        }
        __syncthreads();
#pragma unroll
        for (int it = 0; it < 16; it++) {
            int e = tid + 512*it;
            int mat = e >> 12;
            int idx = e & 4095;
            int i = idx >> 6, j = idx & 63;
            if (mat == 0) {
                M[i][j] = (i == k) ? rkM[j]*ipv : M[i][j] - fcol[i]*rkM[j];
            } else {
                R[i][j] = (i == k) ? rkR[j]*ipv : R[i][j] - fcol[i]*rkR[j];
            }
        }
        __syncthreads();
    }
    for (int idx = tid; idx < 64*64; idx += 512)
        d_Ad[layer*4096 + idx] = R[idx >> 6][idx & 63];
}

// ---------------- S4 recurrence -> d_k (batched output reduction) ----------
__global__ void s4_scan_kernel(const float* __restrict__ s4_B,
                               const float* __restrict__ s4_C) {
    int d = blockIdx.x, layer = blockIdx.y;
    int n = threadIdx.x;               // 64 threads
    __shared__ __align__(8) float xs[2][64];
    __shared__ float stage[2][64][9];  // double-buffered product staging
    unsigned long long ad2[32];
    const float* Adp = d_Ad + layer*4096 + n*64;
#pragma unroll
    for (int j = 0; j < 32; j++) {
        float lo = Adp[2*j], hi = Adp[2*j+1];
        unsigned long long v;
        asm("mov.b64 %0, {%1, %2};" : "=l"(v) : "f"(lo), "f"(hi));
        ad2[j] = v;
    }
    float bcol = s4_B[(layer*Nst + n)*Dsz + d];
    xs[0][n] = s4_C[(layer*Dsz + d)*Nst + n];
    __syncthreads();
    float* kp = d_k + (layer*Dsz + d)*Tsz;
    int g8 = n >> 3, j8 = n & 7;
    int cur = 0;
    for (int t = 0; t < Tsz; t++) {
        float xn = xs[cur][n];
        int buf = (t >> 3) & 1;
        stage[buf][n][t & 7] = xn * bcol;
        const unsigned long long* xv = reinterpret_cast<const unsigned long long*>(&xs[cur][0]);
        unsigned long long a0 = 0ULL, a1 = 0ULL, a2 = 0ULL, a3 = 0ULL;
#pragma unroll
        for (int j = 0; j < 8; j++) {
            a0 = fma2(ad2[j],      xv[j],      a0);
            a1 = fma2(ad2[j + 8],  xv[j + 8],  a1);
            a2 = fma2(ad2[j + 16], xv[j + 16], a2);
            a3 = fma2(ad2[j + 24], xv[j + 24], a3);
        }
        float2 f0 = unpack2(a0), f1 = unpack2(a1), f2 = unpack2(a2), f3 = unpack2(a3);
        float acc = ((f0.x + f0.y) + (f1.x + f1.y)) + ((f2.x + f2.y) + (f3.x + f3.y));
        xs[cur ^ 1][n] = fminf(fmaxf(acc, -100.0f), 100.0f);
        __syncthreads();
        if ((t & 7) == 7) {
            float s = 0.f;
#pragma unroll
            for (int m = 0; m < 8; m++) s += stage[buf][j8 + 8*m][g8];
            s += __shfl_xor_sync(0xffffffffu, s, 4);
            s += __shfl_xor_sync(0xffffffffu, s, 2);
            s += __shfl_xor_sync(0xffffffffu, s, 1);
            if (j8 == 0) {
                int tt = t - 7 + g8;
                float ks = fminf(fmaxf(s, -10.0f), 10.0f);
                kp[tt] = ks * expf(-0.01f * (float)tt);
            }
        }
        cur ^= 1;
    }
}

// ---------------- radix-8 butterfly with twiddle ----------------
__device__ __forceinline__ void bf8(C2* v, C2 w1) {
    C2 t0 = cadd(v[0], v[4]), t1 = csub(v[0], v[4]);
    C2 t2 = cadd(v[2], v[6]), t3 = cmulni(csub(v[2], v[6]));
    C2 e0 = cadd(t0, t2), e1 = cadd(t1, t3), e2 = csub(t0, t2), e3 = csub(t1, t3);
    C2 u0 = cadd(v[1], v[5]), u1 = csub(v[1], v[5]);
    C2 u2 = cadd(v[3], v[7]), u3 = cmulni(csub(v[3], v[7]));
    C2 o0 = cadd(u0, u2), o1 = cadd(u1, u3), o2 = csub(u0, u2), o3 = csub(u1, u3);
    const float c = 0.70710678118654752440f;
    C2 q1; q1.x = c*(o1.x + o1.y); q1.y = c*(o1.y - o1.x);
    C2 q2 = cmulni(o2);
    C2 q3; q3.x = c*(o3.y - o3.x); q3.y = -c*(o3.x + o3.y);
    v[0] = cadd(e0, o0); v[1] = cadd(e1, q1); v[2] = cadd(e2, q2); v[3] = cadd(e3, q3);
    v[4] = csub(e0, o0); v[5] = csub(e1, q1); v[6] = csub(e2, q2); v[7] = csub(e3, q3);
    C2 w2 = cmul(w1, w1), w3 = cmul(w2, w1), w4 = cmul(w2, w2);
    C2 w5 = cmul(w4, w1), w6 = cmul(w4, w2), w7 = cmul(w4, w3);
    v[1] = cmul(v[1], w1); v[2] = cmul(v[2], w2); v[3] = cmul(v[3], w3);
    v[4] = cmul(v[4], w4); v[5] = cmul(v[5], w5); v[6] = cmul(v[6], w6); v[7] = cmul(v[7], w7);
}

// in-place Stockham radix-8 stage on ONE buffer pair: load->bf8->BAR->store
__device__ __forceinline__ void stage8ip(float* sr, float* si,
                                         const float* twr, const float* twi,
                                         int p, int q, int s) {
    C2 v[8];
    int base = q + s*p;
#pragma unroll
    for (int k = 0; k < 8; k++) {
        int ix = PD(base + 256*k);
        v[k].x = sr[ix]; v[k].y = si[ix];
    }
    int j = PD(p*s);
    C2 w1; w1.x = twr[j]; w1.y = twi[j];
    bf8(v, w1);
    __syncthreads();           // all loads complete before any store
    int wb = q + 8*s*p;
#pragma unroll
    for (int k = 0; k < 8; k++) {
        int ix = PD(wb + s*k);
        sr[ix] = v[k].x; si[ix] = v[k].y;
    }
}

// full 2048 FFT, fully in-place on (pr, pi). 256 threads.
// Identical arithmetic/order to the ping-pong version; half the smem.
__device__ __forceinline__ void fft2048s(float* pr, float* pi,
                                         const float* twr, const float* twi) {
    int tid = threadIdx.x;
    __syncthreads();   // input visible
    stage8ip(pr, pi, twr, twi, tid, 0, 1);             // n=2048, s=1
    __syncthreads();
    stage8ip(pr, pi, twr, twi, tid & 31, tid >> 5, 8); // n=256, s=8
    __syncthreads();
    stage8ip(pr, pi, twr, twi, tid >> 6, tid & 63, 64);// n=32, s=64
    __syncthreads();
    // radix-4, s=512, no twiddle; reads and writes the SAME per-thread
    // addresses -> in-place per-thread, no barrier needed inside
#pragma unroll
    for (int h = 0; h < 2; h++) {
        int q = tid + 256*h;
        int o0 = PD(q), o1 = PD(q + 512), o2 = PD(q + 1024), o3 = PD(q + 1536);
        C2 x0; x0.x = pr[o0]; x0.y = pi[o0];
        C2 x1; x1.x = pr[o1]; x1.y = pi[o1];
        C2 x2; x2.x = pr[o2]; x2.y = pi[o2];
        C2 x3; x3.x = pr[o3]; x3.y = pi[o3];
        C2 t0 = cadd(x0, x2), t1 = csub(x0, x2);
        C2 t2 = cadd(x1, x3), t3 = cmulni(csub(x1, x3));
        pr[o0] = t0.x + t2.x; pi[o0] = t0.y + t2.y;
        pr[o1] = t1.x + t3.x; pi[o1] = t1.y + t3.y;
        pr[o2] = t0.x - t2.x; pi[o2] = t0.y - t2.y;
        pr[o3] = t1.x - t3.x; pi[o3] = t1.y - t3.y;
    }
    __syncthreads();   // result visible
}

// ---------------- kernel spectra: pack 2 d's per FFT ----------------
__global__ void fft_k_kernel() {
    __shared__ float ar[2112], ai[2112];
    __shared__ float twr_s[264], twi_s[264];
    int tid = threadIdx.x;
    int dp = blockIdx.x, layer = blockIdx.y;
    int d0 = dp*2, d1 = dp*2 + 1;
    twr_s[PD(tid)] = d_twr[tid];
    twi_s[PD(tid)] = d_twi[tid];
    const float* k0 = d_k + (layer*Dsz + d0)*Tsz;
    const float* k1 = d_k + (layer*Dsz + d1)*Tsz;
#pragma unroll
    for (int q = 0; q < 8; q++) {
        int t = tid + 256*q;
        float v0 = (t < Tsz) ? k0[t] : 0.0f;
        float v1 = (t < Tsz) ? k1[t] : 0.0f;
        ar[PD(t)] = v0; ai[PD(t)] = v1;
    }
    fft2048s(ar, ai, twr_s, twi_s);
    float2* K0 = d_kf + (layer*Dsz + d0)*FFTN;
    float2* K1 = d_kf + (layer*Dsz + d1)*FFTN;
#pragma unroll
    for (int q = 0; q < 8; q++) {
        int f = tid + 256*q;
        int fm = (FFTN - f) & (FFTN - 1);
        C2 Zf; Zf.x = ar[PD(f)];  Zf.y = ai[PD(f)];
        C2 Zm; Zm.x = ar[PD(fm)]; Zm.y = ai[PD(fm)];
        K0[f] = make_float2(0.5f*(Zf.x + Zm.x), 0.5f*(Zf.y - Zm.y));
        K1[f] = make_float2(0.5f*(Zf.y + Zm.y), 0.5f*(Zm.x - Zf.x));
    }
}

// ---------------- input projection (raw) -> d_xt as (B,T,D) ----------------
__global__ void in_proj_kernel(const float* __restrict__ x,
                               const float* __restrict__ b_in) {
    int b = blockIdx.x, t0 = blockIdx.y * 20;
    int tid = threadIdx.x;
    __shared__ float ws[32][256];
    __shared__ float xs[32][20];
    float acc[20];
#pragma unroll
    for (int j = 0; j < 20; j++) acc[j] = 0.0f;
    for (int c0 = 0; c0 < Csz; c0 += 32) {
        __syncthreads();
#pragma unroll
        for (int i = 0; i < 32; i++)
            ws[i][tid] = (c0 + i < Csz) ? d_wt[(c0 + i)*Dsz + tid] : 0.0f;
        for (int l = tid; l < 640; l += 256) {
            int cc = l / 20, j = l % 20;
            xs[cc][j] = (c0 + cc < Csz) ? x[(b*Csz + c0 + cc)*Tsz + t0 + j] : 0.0f;
        }
        __syncthreads();
#pragma unroll
        for (int cc = 0; cc < 32; cc++) {
            float wv = ws[cc][tid];
#pragma unroll
            for (int j = 0; j < 20; j++) acc[j] += wv * xs[cc][j];
        }
    }
    float bias = b_in[tid];
#pragma unroll
    for (int j = 0; j < 20; j++)
        d_xt[(b*Tsz + t0 + j)*Dsz + tid] = acc[j] + bias;
}

// ---- fused: layernorm + pos encoding -> d_h; L2-norm + transpose -> d_xt2 --
__global__ void ln_pos_norm_t_kernel(const float* __restrict__ g,
                                     const float* __restrict__ bb) {
    __shared__ float tile[32][257];
    int b = blockIdx.x, t0 = blockIdx.y * 32;
    int tid = threadIdx.x, lane = tid & 31, w = tid >> 5;
#pragma unroll
    for (int j = 0; j < 4; j++) {
        int r = w + 8*j;
        int t = t0 + r;
        if (t >= Tsz) continue;
        const float* src = d_xt + (b*Tsz + t)*Dsz;
        float v[8]; float s = 0.f, s2 = 0.f;
#pragma unroll
        for (int k = 0; k < 8; k++) {
            float xv = src[lane + 32*k];
            v[k] = xv; s += xv; s2 += xv*xv;
        }
#pragma unroll
        for (int off = 16; off; off >>= 1) {
            s  += __shfl_xor_sync(0xffffffffu, s,  off);
            s2 += __shfl_xor_sync(0xffffffffu, s2, off);
        }
        float m = s * (1.0f/256.0f);
        float var = s2 * (1.0f/256.0f) - m*m;
        float is = rsqrtf(var + 1e-5f);
        float* dst = d_h + (b*Tsz + t)*Dsz;
        const float* pe = d_pe + t*Dsz;
        float o[8]; float ss = 0.f;
#pragma unroll
        for (int k = 0; k < 8; k++) {
            int dd = lane + 32*k;
            float ov = (v[k] - m)*is*g[dd] + bb[dd] + pe[dd];
            o[k] = ov; ss += ov*ov;
            dst[dd] = ov;
        }
#pragma unroll
        for (int off = 16; off; off >>= 1) ss += __shfl_xor_sync(0xffffffffu, ss, off);
        float invn = 1.0f / (sqrtf(ss) + 1e-8f);
#pragma unroll
        for (int k = 0; k < 8; k++) tile[r][lane + 32*k] = o[k]*invn;
    }
    __syncthreads();
#pragma unroll
    for (int i = 0; i < 32; i++) {
        int dd = i*8 + w;
        int t = t0 + lane;
        if (t < Tsz) d_xt2[(b*Dsz + dd)*Tsz + t] = tile[lane][dd];
    }
}

// ---------------- packed FFT convolution + gate, in-place on d_xt2 ----------
__global__ void fft_conv_kernel(int layer, const float* __restrict__ s4_D) {
    __shared__ float ar[2112], ai[2112];
    __shared__ float twr_s[264], twi_s[264];
    int tid = threadIdx.x;
    int b = blockIdx.x, dp = blockIdx.y;
    int d0 = dp*2, d1 = dp*2 + 1;
    twr_s[PD(tid)] = d_twr[tid];
    twi_s[PD(tid)] = d_twi[tid];
    float* x0 = d_xt2 + (b*Dsz + d0)*Tsz;
    float* x1 = d_xt2 + (b*Dsz + d1)*Tsz;
    float xr0[4], xr1[4];
#pragma unroll
    for (int q = 0; q < 8; q++) {
        int t = tid + 256*q;
        float v0 = 0.0f, v1 = 0.0f;
        if (t < Tsz) { v0 = x0[t]; v1 = x1[t]; }
        if (q < 4) { xr0[q] = v0; xr1[q] = v1; }
        ar[PD(t)] = v0; ai[PD(t)] = v1;
    }
    fft2048s(ar, ai, twr_s, twi_s);   // Z in place
    const float2* K0 = d_kf + (layer*Dsz + d0)*FFTN;
    const float2* K1 = d_kf + (layer*Dsz + d1)*FFTN;
    // spectral multiply in place: read all (Zf, Zm) pairs into registers,
    // barrier, then overwrite
    float rr[8], ri[8];
#pragma unroll
    for (int q = 0; q < 8; q++) {
        int f = tid + 256*q;
        int fm = (FFTN - f) & (FFTN - 1);
        C2 Zf; Zf.x = ar[PD(f)];  Zf.y = ai[PD(f)];
        C2 Zm; Zm.x = ar[PD(fm)]; Zm.y = ai[PD(fm)];
        C2 X0; X0.x = 0.5f*(Zf.x + Zm.x); X0.y = 0.5f*(Zf.y - Zm.y);
        C2 X1; X1.x = 0.5f*(Zf.y + Zm.y); X1.y = 0.5f*(Zm.x - Zf.x);
        float2 k0 = K0[f], k1 = K1[f];
        C2 c0; c0.x = k0.x; c0.y = k0.y;
        C2 c1; c1.x = k1.x; c1.y = k1.y;
        C2 Y0 = cmul(X0, c0);
        C2 Y1 = cmul(X1, c1);
        rr[q] = Y0.x - Y1.y;           // conj(S), S = Y0 + i*Y1
        ri[q] = -(Y0.y + Y1.x);
    }
    __syncthreads();
#pragma unroll
    for (int q = 0; q < 8; q++) {
        int f = tid + 256*q;
        ar[PD(f)] = rr[q]; ai[PD(f)] = ri[q];
    }
    fft2048s(ar, ai, twr_s, twi_s);   // V in place; ifft = conj(V)/N
    float g0 = 1.0f / (1.0f + expf(-s4_D[layer*Dsz + d0]));
    float g1 = 1.0f / (1.0f + expf(-s4_D[layer*Dsz + d1]));
    const float inv = 1.0f / (float)FFTN;
#pragma unroll
    for (int q = 0; q < 4; q++) {
        int t = tid + 256*q;
        if (t < Tsz) {
            x0[t] =  ar[PD(t)]*inv + xr0[q]*g0;
            x1[t] = -ai[PD(t)]*inv + xr1[q]*g1;
        }
    }
}

// ---- fused: gelu + residual + LN -> d_h; L2-norm + transpose -> d_xt2 ------
__global__ void post_ln_norm_t_kernel(int layer, int last,
                                      const float* __restrict__ ln_g,
                                      const float* __restrict__ ln_b) {
    __shared__ float tile[32][257];
    int b = blockIdx.x, t0 = blockIdx.y * 32;
    int tid = threadIdx.x, lane = tid & 31, w = tid >> 5;
#pragma unroll
    for (int i = 0; i < 32; i++) {
        int dd = i*8 + w;
        int t = t0 + lane;
        tile[lane][dd] = (t < Tsz) ? d_xt2[(b*Dsz + dd)*Tsz + t] : 0.0f;
    }
    __syncthreads();
    const float* g  = ln_g + layer*Dsz;
    const float* bb = ln_b + layer*Dsz;
#pragma unroll
    for (int j = 0; j < 4; j++) {
        int r = w + 8*j;
        int t = t0 + r;
        if (t >= Tsz) continue;
        float z[8]; float s = 0.f, s2 = 0.f;
        float* hp = d_h + (b*Tsz + t)*Dsz;
#pragma unroll
        for (int k = 0; k < 8; k++) {
            int dd = lane + 32*k;
            float y = tile[r][dd];
            float hv = hp[dd];
            float gl = 0.5f*y*(1.0f + erff(y*0.70710678118654752f));
            float zz = gl + 1.1f*hv;
            z[k] = zz; s += zz; s2 += zz*zz;
        }
#pragma unroll
        for (int off = 16; off; off >>= 1) {
            s  += __shfl_xor_sync(0xffffffffu, s,  off);
            s2 += __shfl_xor_sync(0xffffffffu, s2, off);
        }
        float m = s * (1.0f/256.0f);
        float var = s2 * (1.0f/256.0f) - m*m;
        float is = rsqrtf(var + 1e-5f);
        float o[8]; float ss = 0.f;
#pragma unroll
        for (int k = 0; k < 8; k++) {
            int dd = lane + 32*k;
            float ov = (z[k] - m)*is*g[dd] + bb[dd];
            o[k] = ov; ss += ov*ov;
            hp[dd] = ov;
        }
        if (!last) {
#pragma unroll
            for (int off = 16; off; off >>= 1) ss += __shfl_xor_sync(0xffffffffu, ss, off);
            float invn = 1.0f / (sqrtf(ss) + 1e-8f);
#pragma unroll
            for (int k = 0; k < 8; k++) tile[r][lane + 32*k] = o[k]*invn;
        }
    }
    if (last) return;
    __syncthreads();
#pragma unroll
    for (int i = 0; i < 32; i++) {
        int dd = i*8 + w;
        int t = t0 + lane;
        if (t < Tsz) d_xt2[(b*Dsz + dd)*Tsz + t] = tile[lane][dd];
    }
}

// ---------------- fused MHA pooling + head ----------------
__global__ void pool_head_kernel(const float* __restrict__ cls,
                                 const float* __restrict__ in_w,
                                 const float* __restrict__ in_b,
                                 const float* __restrict__ out_w,
                                 const float* __restrict__ out_b,
                                 const float* __restrict__ hw1,
                                 const float* __restrict__ hb1,
                                 const float* __restrict__ hw2,
                                 const float* __restrict__ hb2,
                                 float* __restrict__ out) {
    int b = blockIdx.x;
    int tid = threadIdx.x, lane = tid & 31, w = tid >> 5;
    __shared__ float Q[256];
    __shared__ float vp[8][256];
    __shared__ float sc[8][1001];
    __shared__ float ch[8];
    __shared__ float red[256];
    __shared__ float hsm[128];

    {
        float acc = in_b[tid];
        for (int c = 0; c < 256; c++) acc += cls[c] * in_w[tid*256 + c];
        Q[tid] = acc;
    }
    __syncthreads();
#pragma unroll
    for (int h = 0; h < 8; h++) {
        float acc = 0.f;
#pragma unroll
        for (int i = 0; i < 32; i++)
            acc += in_w[(256 + h*32 + i)*256 + tid] * Q[h*32 + i];
        vp[h][tid] = acc;
    }
    if (tid < 8) {
        float acc = 0.f;
        for (int i = 0; i < 32; i++) acc += in_b[256 + tid*32 + i] * Q[tid*32 + i];
        ch[tid] = acc;
    }
    __syncthreads();
    const float iss = 0.17677669529663687f; // 1/sqrt(32)
    for (int s = w; s < 1001; s += 8) {
        const float* kvr = (s == 0) ? cls : (d_h + (b*Tsz + s - 1)*Dsz);
        float xv[8];
#pragma unroll
        for (int k = 0; k < 8; k++) xv[k] = kvr[lane*8 + k];
#pragma unroll
        for (int h = 0; h < 8; h++) {
            float a = 0.f;
#pragma unroll
            for (int k = 0; k < 8; k++) a += xv[k] * vp[h][lane*8 + k];
#pragma unroll
            for (int off = 16; off; off >>= 1) a += __shfl_xor_sync(0xffffffffu, a, off);
            if (lane == h) sc[h][s] = (a + ch[h]) * iss;
        }
    }
    __syncthreads();
    {
        int h = w;
        float mx = -1e30f;
        for (int s = lane; s < 1001; s += 32) mx = fmaxf(mx, sc[h][s]);
#pragma unroll
        for (int off = 16; off; off >>= 1) mx = fmaxf(mx, __shfl_xor_sync(0xffffffffu, mx, off));
        float sum = 0.f;
        for (int s = lane; s < 1001; s += 32) { float e = expf(sc[h][s] - mx); sc[h][s] = e; sum += e; }
#pragma unroll
        for (int off = 16; off; off >>= 1) sum += __shfl_xor_sync(0xffffffffu, sum, off);
        float invs = 1.0f / sum;
        for (int s = lane; s < 1001; s += 32) sc[h][s] *= invs;
    }
    __syncthreads();
    float pj[8];
#pragma unroll
    for (int h = 0; h < 8; h++) pj[h] = 0.f;
    for (int s = 0; s < 1001; s++) {
        float kvv = (s == 0) ? cls[tid] : d_h[(b*Tsz + s - 1)*Dsz + tid];
#pragma unroll
        for (int h = 0; h < 8; h++) pj[h] += sc[h][s] * kvv;
    }
    __syncthreads();
#pragma unroll
    for (int h = 0; h < 8; h++) vp[h][tid] = pj[h];
    __syncthreads();
    {
        int h = tid >> 5;
        float acc = in_b[512 + tid];
        for (int j = 0; j < 256; j++) acc += in_w[(512 + tid)*256 + j] * vp[h][j];
        Q[tid] = acc;
    }
    __syncthreads();
    {
        float acc = out_b[tid];
        for (int i = 0; i < 256; i++) acc += out_w[tid*256 + i] * Q[i];
        red[tid] = acc;
    }
    __syncthreads();
    if (tid < 128) {
        float acc = hb1[tid];
        for (int i = 0; i < 256; i++) acc += hw1[tid*256 + i] * red[i];
        hsm[tid] = fmaxf(acc, 0.0f);
    }
    __syncthreads();
    if (w == 0) {
        float a = 0.f;
#pragma unroll
        for (int k = 0; k < 4; k++) a += hsm[lane + 32*k] * hw2[lane + 32*k];
#pragma unroll
        for (int off = 16; off; off >>= 1) a += __shfl_xor_sync(0xffffffffu, a, off);
        if (lane == 0) out[b] = a + hb2[0];
    }
}

// ---------------- launch ----------------
extern "C" void kernel_launch(void* const* d_in, const int* in_sizes, int n_in,
                              void* d_out, int out_size) {
    const float* x        = (const float*)d_in[0];
    const float* w_in     = (const float*)d_in[1];
    const float* b_in     = (const float*)d_in[2];
    const float* ln_in_g  = (const float*)d_in[3];
    const float* ln_in_b  = (const float*)d_in[4];
    const float* s4_B     = (const float*)d_in[5];
    const float* s4_C     = (const float*)d_in[6];
    const float* s4_logdt = (const float*)d_in[7];
    const float* s4_D     = (const float*)d_in[8];
    const float* ln_g     = (const float*)d_in[9];
    const float* ln_b     = (const float*)d_in[10];
    const float* cls      = (const float*)d_in[11];
    const float* mha_in_w = (const float*)d_in[12];
    const float* mha_in_b = (const float*)d_in[13];
    const float* mha_out_w= (const float*)d_in[14];
    const float* mha_out_b= (const float*)d_in[15];
    const float* head_w1  = (const float*)d_in[16];
    const float* head_b1  = (const float*)d_in[17];
    const float* head_w2  = (const float*)d_in[18];
    const float* head_b2  = (const float*)d_in[19];
    float* out = (float*)d_out;

    setup_kernel<<<256, 256>>>(w_in);
    compute_Ad_kernel<<<NL, 512>>>(s4_logdt);
    s4_scan_kernel<<<dim3(Dsz, NL), 64>>>(s4_B, s4_C);
    fft_k_kernel<<<dim3(Dsz/2, NL), 256>>>();
    in_proj_kernel<<<dim3(Bsz, 50), 256>>>(x, b_in);
    ln_pos_norm_t_kernel<<<dim3(Bsz, 32), 256>>>(ln_in_g, ln_in_b);
    for (int layer = 0; layer < NL; layer++) {
        fft_conv_kernel<<<dim3(Bsz, Dsz/2), 256>>>(layer, s4_D);
        post_ln_norm_t_kernel<<<dim3(Bsz, 32), 256>>>(layer, (layer == NL-1) ? 1 : 0, ln_g, ln_b);
    }
    pool_head_kernel<<<Bsz, 256>>>(cls, mha_in_w, mha_in_b, mha_out_w, mha_out_b,
                                   head_w1, head_b1, head_w2, head_b2, out);
}

// round 10
// speedup vs baseline: 1.1195x; 1.1195x over previous
#include <cuda_runtime.h>
#include <cuda_bf16.h>
#include <math.h>

#define Bsz 32
#define Csz 129
#define Tsz 1000
#define Dsz 256
#define Nst 64
#define NL  4
#define FFTN 2048

// ---------------- scratch (device globals; no runtime alloc) ----------------
__device__ float  d_h [Bsz*Tsz*Dsz];     // final hidden (B,T,D) for pooling
__device__ float  d_xt[Bsz*Tsz*Dsz];     // raw projection (B,T,D)
__device__ float  d_xt2[Bsz*Tsz*Dsz];    // (B,D,T): normalized x OR conv z, in-place
__device__ float  d_nrm[Bsz*Tsz];        // per (b,t) L2 norm of LN output
__device__ float  d_k [NL*Dsz*Tsz];      // S4 kernels
__device__ float2 d_kf[NL*Dsz*FFTN];     // spectra of kernels
__device__ float  d_Ad[NL*Nst*Nst];
__device__ float  d_twr[256];
__device__ float  d_twi[256];
__device__ float  d_wt[Csz*Dsz];         // transposed w_in
__device__ float  d_pe[Tsz*Dsz];         // positional encoding table

#define PI_D 3.14159265358979323846

// ---------------- complex helpers ----------------
struct C2 { float x, y; };
__device__ __forceinline__ C2 cmul(C2 a, C2 b){ C2 r; r.x = a.x*b.x - a.y*b.y; r.y = a.x*b.y + a.y*b.x; return r; }
__device__ __forceinline__ C2 cadd(C2 a, C2 b){ C2 r; r.x = a.x+b.x; r.y = a.y+b.y; return r; }
__device__ __forceinline__ C2 csub(C2 a, C2 b){ C2 r; r.x = a.x-b.x; r.y = a.y-b.y; return r; }
__device__ __forceinline__ C2 cmulni(C2 a){ C2 r; r.x = a.y; r.y = -a.x; return r; }  // a * (-i)

#define PD(i) ((i) + ((i)>>5))

// ---------------- f32x2 packed fma ----------------
__device__ __forceinline__ unsigned long long fma2(unsigned long long a, unsigned long long b, unsigned long long c){
    unsigned long long d;
    asm("fma.rn.f32x2 %0, %1, %2, %3;" : "=l"(d) : "l"(a), "l"(b), "l"(c));
    return d;
}
__device__ __forceinline__ float2 unpack2(unsigned long long v){
    float2 r; asm("mov.b64 {%0, %1}, %2;" : "=f"(r.x), "=f"(r.y) : "l"(v)); return r;
}

// ---------------- setup: twiddles, w transpose, pos-encoding ----------------
__global__ void setup_kernel(const float* __restrict__ w_in) {
    int idx = blockIdx.x * blockDim.x + threadIdx.x;
    int stride = gridDim.x * blockDim.x;
    if (idx < 256) {
        double ang = -2.0 * PI_D * (double)idx / (double)FFTN;
        d_twr[idx] = (float)cos(ang);
        d_twi[idx] = (float)sin(ang);
    }
    for (int i = idx; i < Csz*Dsz; i += stride) {
        int dd = i / Csz, c = i % Csz;
        d_wt[c*Dsz + dd] = w_in[i];
    }
    for (int i = idx; i < Tsz*Dsz; i += stride) {
        int t = i / Dsz, dd = i % Dsz;
        double divv = exp(-(double)(dd >> 1) * 2.0 * log(10000.0) / (double)Dsz);
        double arg = (double)t * divv;
        d_pe[i] = (float)((dd & 1) ? cos(arg) : sin(arg));
    }
}

// ---------------- Ad = solve(I - dtA, I + dtA): pivot-free Gauss-Jordan -----
__global__ void compute_Ad_kernel(const float* __restrict__ s4_logdt) {
    int layer = blockIdx.x;
    __shared__ float M[64][65];
    __shared__ float R[64][65];
    __shared__ float fcol[64];
    __shared__ float rkM[64];
    __shared__ float rkR[64];
    int tid = threadIdx.x; // 512 threads

    float logdt = s4_logdt[layer*Dsz + 0];
    float dt = fminf(fmaxf(expf(logdt), 1e-4f), 0.1f);
    float hdt = dt * 0.5f;

    for (int idx = tid; idx < 64*64; idx += 512) {
        int i = idx >> 6, j = idx & 63;
        float Pi = sqrtf(1.0f + 2.0f*i), Pj = sqrtf(1.0f + 2.0f*j);
        float a;
        if (i == j)      a = -((float)i + 0.5f);
        else if (i > j)  a = -Pi*Pj;
        else             a =  Pi*Pj;
        float eye = (i == j) ? 1.0f : 0.0f;
        M[i][j] = eye - hdt*a;
        R[i][j] = eye + hdt*a;
    }
    __syncthreads();

    for (int k = 0; k < 64; k++) {
        float ipv = 1.0f / M[k][k];
        if (tid < 64) {
            fcol[tid] = (tid == k) ? 0.0f : M[tid][k] * ipv;
        } else if (tid < 128) {
            int c = tid - 64; rkM[c] = M[k][c];
        } else if (tid < 192) {
            int c = tid - 128; rkR[c] = R[k][c];
        }
        __syncthreads();
#pragma unroll
        for (int it = 0; it < 16; it++) {
            int e = tid + 512*it;
            int mat = e >> 12;
            int idx = e & 4095;
            int i = idx >> 6, j = idx & 63;
            if (mat == 0) {
                M[i][j] = (i == k) ? rkM[j]*ipv : M[i][j] - fcol[i]*rkM[j];
            } else {
                R[i][j] = (i == k) ? rkR[j]*ipv : R[i][j] - fcol[i]*rkR[j];
            }
        }
        __syncthreads();
    }
    for (int idx = tid; idx < 64*64; idx += 512)
        d_Ad[layer*4096 + idx] = R[idx >> 6][idx & 63];
}

// ---------------- S4 recurrence -> d_k (batched output reduction) ----------
__global__ void s4_scan_kernel(const float* __restrict__ s4_B,
                               const float* __restrict__ s4_C) {
    int d = blockIdx.x, layer = blockIdx.y;
    int n = threadIdx.x;               // 64 threads
    __shared__ __align__(8) float xs[2][64];
    __shared__ float stage[2][64][9];  // double-buffered product staging
    unsigned long long ad2[32];
    const float* Adp = d_Ad + layer*4096 + n*64;
#pragma unroll
    for (int j = 0; j < 32; j++) {
        float lo = Adp[2*j], hi = Adp[2*j+1];
        unsigned long long v;
        asm("mov.b64 %0, {%1, %2};" : "=l"(v) : "f"(lo), "f"(hi));
        ad2[j] = v;
    }
    float bcol = s4_B[(layer*Nst + n)*Dsz + d];
    xs[0][n] = s4_C[(layer*Dsz + d)*Nst + n];
    __syncthreads();
    float* kp = d_k + (layer*Dsz + d)*Tsz;
    int g8 = n >> 3, j8 = n & 7;
    int cur = 0;
    for (int t = 0; t < Tsz; t++) {
        float xn = xs[cur][n];
        int buf = (t >> 3) & 1;
        stage[buf][n][t & 7] = xn * bcol;
        const unsigned long long* xv = reinterpret_cast<const unsigned long long*>(&xs[cur][0]);
        unsigned long long a0 = 0ULL, a1 = 0ULL, a2 = 0ULL, a3 = 0ULL;
#pragma unroll
        for (int j = 0; j < 8; j++) {
            a0 = fma2(ad2[j],      xv[j],      a0);
            a1 = fma2(ad2[j + 8],  xv[j + 8],  a1);
            a2 = fma2(ad2[j + 16], xv[j + 16], a2);
            a3 = fma2(ad2[j + 24], xv[j + 24], a3);
        }
        float2 f0 = unpack2(a0), f1 = unpack2(a1), f2 = unpack2(a2), f3 = unpack2(a3);
        float acc = ((f0.x + f0.y) + (f1.x + f1.y)) + ((f2.x + f2.y) + (f3.x + f3.y));
        xs[cur ^ 1][n] = fminf(fmaxf(acc, -100.0f), 100.0f);
        __syncthreads();
        if ((t & 7) == 7) {
            float s = 0.f;
#pragma unroll
            for (int m = 0; m < 8; m++) s += stage[buf][j8 + 8*m][g8];
            s += __shfl_xor_sync(0xffffffffu, s, 4);
            s += __shfl_xor_sync(0xffffffffu, s, 2);
            s += __shfl_xor_sync(0xffffffffu, s, 1);
            if (j8 == 0) {
                int tt = t - 7 + g8;
                float ks = fminf(fmaxf(s, -10.0f), 10.0f);
                kp[tt] = ks * expf(-0.01f * (float)tt);
            }
        }
        cur ^= 1;
    }
}

// ---------------- radix-8 butterfly with twiddle ----------------
__device__ __forceinline__ void bf8(C2* v, C2 w1) {
    C2 t0 = cadd(v[0], v[4]), t1 = csub(v[0], v[4]);
    C2 t2 = cadd(v[2], v[6]), t3 = cmulni(csub(v[2], v[6]));
    C2 e0 = cadd(t0, t2), e1 = cadd(t1, t3), e2 = csub(t0, t2), e3 = csub(t1, t3);
    C2 u0 = cadd(v[1], v[5]), u1 = csub(v[1], v[5]);
    C2 u2 = cadd(v[3], v[7]), u3 = cmulni(csub(v[3], v[7]));
    C2 o0 = cadd(u0, u2), o1 = cadd(u1, u3), o2 = csub(u0, u2), o3 = csub(u1, u3);
    const float c = 0.70710678118654752440f;
    C2 q1; q1.x = c*(o1.x + o1.y); q1.y = c*(o1.y - o1.x);
    C2 q2 = cmulni(o2);
    C2 q3; q3.x = c*(o3.y - o3.x); q3.y = -c*(o3.x + o3.y);
    v[0] = cadd(e0, o0); v[1] = cadd(e1, q1); v[2] = cadd(e2, q2); v[3] = cadd(e3, q3);
    v[4] = csub(e0, o0); v[5] = csub(e1, q1); v[6] = csub(e2, q2); v[7] = csub(e3, q3);
    C2 w2 = cmul(w1, w1), w3 = cmul(w2, w1), w4 = cmul(w2, w2);
    C2 w5 = cmul(w4, w1), w6 = cmul(w4, w2), w7 = cmul(w4, w3);
    v[1] = cmul(v[1], w1); v[2] = cmul(v[2], w2); v[3] = cmul(v[3], w3);
    v[4] = cmul(v[4], w4); v[5] = cmul(v[5], w5); v[6] = cmul(v[6], w6); v[7] = cmul(v[7], w7);
}

// one Stockham radix-8 stage: reads src at q+s*p (+256k), writes dst at q+8sp (+sk)
__device__ __forceinline__ void stage8(const float* sr, const float* si,
                                       float* dr, float* di,
                                       const float* twr, const float* twi,
                                       int p, int q, int s) {
    C2 v[8];
    int base = q + s*p;
#pragma unroll
    for (int k = 0; k < 8; k++) {
        int ix = PD(base + 256*k);
        v[k].x = sr[ix]; v[k].y = si[ix];
    }
    int j = PD(p*s);
    C2 w1; w1.x = twr[j]; w1.y = twi[j];
    bf8(v, w1);
    int wb = q + 8*s*p;
#pragma unroll
    for (int k = 0; k < 8; k++) {
        int ix = PD(wb + s*k);
        dr[ix] = v[k].x; di[ix] = v[k].y;
    }
}

// full 2048 FFT: input AND result in (pr, pi); (qr, qi) is scratch. 256 threads.
__device__ __forceinline__ void fft2048s(float* pr, float* pi, float* qr, float* qi,
                                         const float* twr, const float* twi) {
    int tid = threadIdx.x;
    __syncthreads();   // input visible
    stage8(pr, pi, qr, qi, twr, twi, tid, 0, 1);             // n=2048, s=1
    __syncthreads();
    stage8(qr, qi, pr, pi, twr, twi, tid & 31, tid >> 5, 8); // n=256, s=8
    __syncthreads();
    stage8(pr, pi, qr, qi, twr, twi, tid >> 6, tid & 63, 64);// n=32, s=64
    __syncthreads();
    // radix-4, n=4, s=512, no twiddle; 2 butterflies/thread
#pragma unroll
    for (int h = 0; h < 2; h++) {
        int q = tid + 256*h;
        C2 x0; x0.x = qr[PD(q)];        x0.y = qi[PD(q)];
        C2 x1; x1.x = qr[PD(q + 512)];  x1.y = qi[PD(q + 512)];
        C2 x2; x2.x = qr[PD(q + 1024)]; x2.y = qi[PD(q + 1024)];
        C2 x3; x3.x = qr[PD(q + 1536)]; x3.y = qi[PD(q + 1536)];
        C2 t0 = cadd(x0, x2), t1 = csub(x0, x2);
        C2 t2 = cadd(x1, x3), t3 = cmulni(csub(x1, x3));
        int o0 = PD(q), o1 = PD(q + 512), o2 = PD(q + 1024), o3 = PD(q + 1536);
        pr[o0] = t0.x + t2.x; pi[o0] = t0.y + t2.y;
        pr[o1] = t1.x + t3.x; pi[o1] = t1.y + t3.y;
        pr[o2] = t0.x - t2.x; pi[o2] = t0.y - t2.y;
        pr[o3] = t1.x - t3.x; pi[o3] = t1.y - t3.y;
    }
    __syncthreads();   // result visible
}

// ---------------- kernel spectra: pack 2 d's per FFT ----------------
__global__ void fft_k_kernel() {
    __shared__ float ar[2112], ai[2112], br[2112], bi[2112];
    __shared__ float twr_s[264], twi_s[264];
    int tid = threadIdx.x;
    int dp = blockIdx.x, layer = blockIdx.y;
    int d0 = dp*2, d1 = dp*2 + 1;
    twr_s[PD(tid)] = d_twr[tid];
    twi_s[PD(tid)] = d_twi[tid];
    const float* k0 = d_k + (layer*Dsz + d0)*Tsz;
    const float* k1 = d_k + (layer*Dsz + d1)*Tsz;
#pragma unroll
    for (int q = 0; q < 8; q++) {
        int t = tid + 256*q;
        float v0 = (t < Tsz) ? k0[t] : 0.0f;
        float v1 = (t < Tsz) ? k1[t] : 0.0f;
        ar[PD(t)] = v0; ai[PD(t)] = v1;
    }
    fft2048s(ar, ai, br, bi, twr_s, twi_s);
    float2* K0 = d_kf + (layer*Dsz + d0)*FFTN;
    float2* K1 = d_kf + (layer*Dsz + d1)*FFTN;
#pragma unroll
    for (int q = 0; q < 8; q++) {
        int f = tid + 256*q;
        int fm = (FFTN - f) & (FFTN - 1);
        C2 Zf; Zf.x = ar[PD(f)];  Zf.y = ai[PD(f)];
        C2 Zm; Zm.x = ar[PD(fm)]; Zm.y = ai[PD(fm)];
        K0[f] = make_float2(0.5f*(Zf.x + Zm.x), 0.5f*(Zf.y - Zm.y));
        K1[f] = make_float2(0.5f*(Zf.y + Zm.y), 0.5f*(Zm.x - Zf.x));
    }
}

// ---------------- input projection (raw) -> d_xt as (B,T,D) ----------------
__global__ void in_proj_kernel(const float* __restrict__ x,
                               const float* __restrict__ b_in) {
    int b = blockIdx.x, t0 = blockIdx.y * 20;
    int tid = threadIdx.x;
    __shared__ float ws[32][256];
    __shared__ float xs[32][20];
    float acc[20];
#pragma unroll
    for (int j = 0; j < 20; j++) acc[j] = 0.0f;
    for (int c0 = 0; c0 < Csz; c0 += 32) {
        __syncthreads();
#pragma unroll
        for (int i = 0; i < 32; i++)
            ws[i][tid] = (c0 + i < Csz) ? d_wt[(c0 + i)*Dsz + tid] : 0.0f;
        for (int l = tid; l < 640; l += 256) {
            int cc = l / 20, j = l % 20;
            xs[cc][j] = (c0 + cc < Csz) ? x[(b*Csz + c0 + cc)*Tsz + t0 + j] : 0.0f;
        }
        __syncthreads();
#pragma unroll
        for (int cc = 0; cc < 32; cc++) {
            float wv = ws[cc][tid];
#pragma unroll
            for (int j = 0; j < 20; j++) acc[j] += wv * xs[cc][j];
        }
    }
    float bias = b_in[tid];
#pragma unroll
    for (int j = 0; j < 20; j++)
        d_xt[(b*Tsz + t0 + j)*Dsz + tid] = acc[j] + bias;
}

// ---- fused: LN + pos-enc, L2-normalize, transpose -> d_xt2; store norms ----
__global__ void ln_pos_norm_t_kernel(const float* __restrict__ g,
                                     const float* __restrict__ bb) {
    __shared__ float tile[32][257];
    int b = blockIdx.x, t0 = blockIdx.y * 32;
    int tid = threadIdx.x, lane = tid & 31, w = tid >> 5;
#pragma unroll
    for (int j = 0; j < 4; j++) {
        int r = w + 8*j;
        int t = t0 + r;
        if (t >= Tsz) continue;
        const float* src = d_xt + (b*Tsz + t)*Dsz;
        float v[8]; float s = 0.f, s2 = 0.f;
#pragma unroll
        for (int k = 0; k < 8; k++) {
            float xv = src[lane + 32*k];
            v[k] = xv; s += xv; s2 += xv*xv;
        }
#pragma unroll
        for (int off = 16; off; off >>= 1) {
            s  += __shfl_xor_sync(0xffffffffu, s,  off);
            s2 += __shfl_xor_sync(0xffffffffu, s2, off);
        }
        float m = s * (1.0f/256.0f);
        float var = s2 * (1.0f/256.0f) - m*m;
        float is = rsqrtf(var + 1e-5f);
        const float* pe = d_pe + t*Dsz;
        float o[8]; float ss = 0.f;
#pragma unroll
        for (int k = 0; k < 8; k++) {
            int dd = lane + 32*k;
            float ov = (v[k] - m)*is*g[dd] + bb[dd] + pe[dd];
            o[k] = ov; ss += ov*ov;
        }
#pragma unroll
        for (int off = 16; off; off >>= 1) ss += __shfl_xor_sync(0xffffffffu, ss, off);
        float nrm = sqrtf(ss) + 1e-8f;
        float invn = 1.0f / nrm;
        if (lane == 0) d_nrm[b*Tsz + t] = nrm;
#pragma unroll
        for (int k = 0; k < 8; k++) tile[r][lane + 32*k] = o[k]*invn;
    }
    __syncthreads();
#pragma unroll
    for (int i = 0; i < 32; i++) {
        int dd = i*8 + w;
        int t = t0 + lane;
        if (t < Tsz) d_xt2[(b*Dsz + dd)*Tsz + t] = tile[lane][dd];
    }
}

// -------- FFT conv + gate + gelu + residual (z = gelu(y)+1.1h), in-place ----
__global__ void fft_conv_kernel(int layer, const float* __restrict__ s4_D) {
    __shared__ float ar[2112], ai[2112], br[2112], bi[2112];
    __shared__ float twr_s[264], twi_s[264];
    int tid = threadIdx.x;
    int b = blockIdx.x, dp = blockIdx.y;
    int d0 = dp*2, d1 = dp*2 + 1;
    twr_s[PD(tid)] = d_twr[tid];
    twi_s[PD(tid)] = d_twi[tid];
    float* x0 = d_xt2 + (b*Dsz + d0)*Tsz;
    float* x1 = d_xt2 + (b*Dsz + d1)*Tsz;
    const float* np = d_nrm + b*Tsz;
    float xr0[4], xr1[4], nr[4];
#pragma unroll
    for (int q = 0; q < 8; q++) {
        int t = tid + 256*q;
        float v0 = 0.0f, v1 = 0.0f;
        if (t < Tsz) { v0 = x0[t]; v1 = x1[t]; }
        if (q < 4) {
            xr0[q] = v0; xr1[q] = v1;
            nr[q] = (t < Tsz) ? np[t] : 0.0f;
        }
        ar[PD(t)] = v0; ai[PD(t)] = v1;
    }
    fft2048s(ar, ai, br, bi, twr_s, twi_s);   // Z in ar/ai
    const float2* K0 = d_kf + (layer*Dsz + d0)*FFTN;
    const float2* K1 = d_kf + (layer*Dsz + d1)*FFTN;
#pragma unroll
    for (int q = 0; q < 8; q++) {
        int f = tid + 256*q;
        int fm = (FFTN - f) & (FFTN - 1);
        C2 Zf; Zf.x = ar[PD(f)];  Zf.y = ai[PD(f)];
        C2 Zm; Zm.x = ar[PD(fm)]; Zm.y = ai[PD(fm)];
        C2 X0; X0.x = 0.5f*(Zf.x + Zm.x); X0.y = 0.5f*(Zf.y - Zm.y);
        C2 X1; X1.x = 0.5f*(Zf.y + Zm.y); X1.y = 0.5f*(Zm.x - Zf.x);
        float2 k0 = K0[f], k1 = K1[f];
        C2 c0; c0.x = k0.x; c0.y = k0.y;
        C2 c1; c1.x = k1.x; c1.y = k1.y;
        C2 Y0 = cmul(X0, c0);
        C2 Y1 = cmul(X1, c1);
        br[PD(f)] = Y0.x - Y1.y;           // conj(S), S = Y0 + i*Y1
        bi[PD(f)] = -(Y0.y + Y1.x);
    }
    fft2048s(br, bi, ar, ai, twr_s, twi_s);   // V in br/bi; ifft = conj(V)/N
    float gate0 = 1.0f / (1.0f + expf(-s4_D[layer*Dsz + d0]));
    float gate1 = 1.0f / (1.0f + expf(-s4_D[layer*Dsz + d1]));
    const float inv = 1.0f / (float)FFTN;
#pragma unroll
    for (int q = 0; q < 4; q++) {
        int t = tid + 256*q;
        if (t < Tsz) {
            float y0 =  br[PD(t)]*inv + xr0[q]*gate0;
            float y1 = -bi[PD(t)]*inv + xr1[q]*gate1;
            float gl0 = 0.5f*y0*(1.0f + erff(y0*0.70710678118654752f));
            float gl1 = 0.5f*y1*(1.0f + erff(y1*0.70710678118654752f));
            x0[t] = gl0 + 1.1f*xr0[q]*nr[q];   // z = gelu(y) + 1.1*h
            x1[t] = gl1 + 1.1f*xr1[q]*nr[q];
        }
    }
}

// ---- post: LN(z); last -> d_h (B,T,D); else normalized transposed + norms --
__global__ void post_ln_norm_t_kernel(int layer, int last,
                                      const float* __restrict__ ln_g,
                                      const float* __restrict__ ln_b) {
    __shared__ float tile[32][257];
    int b = blockIdx.x, t0 = blockIdx.y * 32;
    int tid = threadIdx.x, lane = tid & 31, w = tid >> 5;
#pragma unroll
    for (int i = 0; i < 32; i++) {
        int dd = i*8 + w;
        int t = t0 + lane;
        tile[lane][dd] = (t < Tsz) ? d_xt2[(b*Dsz + dd)*Tsz + t] : 0.0f;
    }
    __syncthreads();
    const float* g  = ln_g + layer*Dsz;
    const float* bb = ln_b + layer*Dsz;
#pragma unroll
    for (int j = 0; j < 4; j++) {
        int r = w + 8*j;
        int t = t0 + r;
        if (t >= Tsz) continue;
        float z[8]; float s = 0.f, s2 = 0.f;
#pragma unroll
        for (int k = 0; k < 8; k++) {
            float zz = tile[r][lane + 32*k];
            z[k] = zz; s += zz; s2 += zz*zz;
        }
#pragma unroll
        for (int off = 16; off; off >>= 1) {
            s  += __shfl_xor_sync(0xffffffffu, s,  off);
            s2 += __shfl_xor_sync(0xffffffffu, s2, off);
        }
        float m = s * (1.0f/256.0f);
        float var = s2 * (1.0f/256.0f) - m*m;
        float is = rsqrtf(var + 1e-5f);
        if (last) {
            float* hp = d_h + (b*Tsz + t)*Dsz;
#pragma unroll
            for (int k = 0; k < 8; k++) {
                int dd = lane + 32*k;
                hp[dd] = (z[k] - m)*is*g[dd] + bb[dd];
            }
        } else {
            float o[8]; float ss = 0.f;
#pragma unroll
            for (int k = 0; k < 8; k++) {
                int dd = lane + 32*k;
                float ov = (z[k] - m)*is*g[dd] + bb[dd];
                o[k] = ov; ss += ov*ov;
            }
#pragma unroll
            for (int off = 16; off; off >>= 1) ss += __shfl_xor_sync(0xffffffffu, ss, off);
            float nrm = sqrtf(ss) + 1e-8f;
            float invn = 1.0f / nrm;
            if (lane == 0) d_nrm[b*Tsz + t] = nrm;
#pragma unroll
            for (int k = 0; k < 8; k++) tile[r][lane + 32*k] = o[k]*invn;
        }
    }
    if (last) return;
    __syncthreads();
#pragma unroll
    for (int i = 0; i < 32; i++) {
        int dd = i*8 + w;
        int t = t0 + lane;
        if (t < Tsz) d_xt2[(b*Dsz + dd)*Tsz + t] = tile[lane][dd];
    }
}

// ---------------- fused MHA pooling + head ----------------
__global__ void pool_head_kernel(const float* __restrict__ cls,
                                 const float* __restrict__ in_w,
                                 const float* __restrict__ in_b,
                                 const float* __restrict__ out_w,
                                 const float* __restrict__ out_b,
                                 const float* __restrict__ hw1,
                                 const float* __restrict__ hb1,
                                 const float* __restrict__ hw2,
                                 const float* __restrict__ hb2,
                                 float* __restrict__ out) {
    int b = blockIdx.x;
    int tid = threadIdx.x, lane = tid & 31, w = tid >> 5;
    __shared__ float Q[256];
    __shared__ float vp[8][256];
    __shared__ float sc[8][1001];
    __shared__ float ch[8];
    __shared__ float red[256];
    __shared__ float hsm[128];

    {
        float acc = in_b[tid];
        for (int c = 0; c < 256; c++) acc += cls[c] * in_w[tid*256 + c];
        Q[tid] = acc;
    }
    __syncthreads();
#pragma unroll
    for (int h = 0; h < 8; h++) {
        float acc = 0.f;
#pragma unroll
        for (int i = 0; i < 32; i++)
            acc += in_w[(256 + h*32 + i)*256 + tid] * Q[h*32 + i];
        vp[h][tid] = acc;
    }
    if (tid < 8) {
        float acc = 0.f;
        for (int i = 0; i < 32; i++) acc += in_b[256 + tid*32 + i] * Q[tid*32 + i];
        ch[tid] = acc;
    }
    __syncthreads();
    const float iss = 0.17677669529663687f; // 1/sqrt(32)
    for (int s = w; s < 1001; s += 8) {
        const float* kvr = (s == 0) ? cls : (d_h + (b*Tsz + s - 1)*Dsz);
        float xv[8];
#pragma unroll
        for (int k = 0; k < 8; k++) xv[k] = kvr[lane*8 + k];
#pragma unroll
        for (int h = 0; h < 8; h++) {
            float a = 0.f;
#pragma unroll
            for (int k = 0; k < 8; k++) a += xv[k] * vp[h][lane*8 + k];
#pragma unroll
            for (int off = 16; off; off >>= 1) a += __shfl_xor_sync(0xffffffffu, a, off);
            if (lane == h) sc[h][s] = (a + ch[h]) * iss;
        }
    }
    __syncthreads();
    {
        int h = w;
        float mx = -1e30f;
        for (int s = lane; s < 1001; s += 32) mx = fmaxf(mx, sc[h][s]);
#pragma unroll
        for (int off = 16; off; off >>= 1) mx = fmaxf(mx, __shfl_xor_sync(0xffffffffu, mx, off));
        float sum = 0.f;
        for (int s = lane; s < 1001; s += 32) { float e = expf(sc[h][s] - mx); sc[h][s] = e; sum += e; }
#pragma unroll
        for (int off = 16; off; off >>= 1) sum += __shfl_xor_sync(0xffffffffu, sum, off);
        float invs = 1.0f / sum;
        for (int s = lane; s < 1001; s += 32) sc[h][s] *= invs;
    }
    __syncthreads();
    float pj[8];
#pragma unroll
    for (int h = 0; h < 8; h++) pj[h] = 0.f;
    for (int s = 0; s < 1001; s++) {
        float kvv = (s == 0) ? cls[tid] : d_h[(b*Tsz + s - 1)*Dsz + tid];
#pragma unroll
        for (int h = 0; h < 8; h++) pj[h] += sc[h][s] * kvv;
    }
    __syncthreads();
#pragma unroll
    for (int h = 0; h < 8; h++) vp[h][tid] = pj[h];
    __syncthreads();
    {
        int h = tid >> 5;
        float acc = in_b[512 + tid];
        for (int j = 0; j < 256; j++) acc += in_w[(512 + tid)*256 + j] * vp[h][j];
        Q[tid] = acc;
    }
    __syncthreads();
    {
        float acc = out_b[tid];
        for (int i = 0; i < 256; i++) acc += out_w[tid*256 + i] * Q[i];
        red[tid] = acc;
    }
    __syncthreads();
    if (tid < 128) {
        float acc = hb1[tid];
        for (int i = 0; i < 256; i++) acc += hw1[tid*256 + i] * red[i];
        hsm[tid] = fmaxf(acc, 0.0f);
    }
    __syncthreads();
    if (w == 0) {
        float a = 0.f;
#pragma unroll
        for (int k = 0; k < 4; k++) a += hsm[lane + 32*k] * hw2[lane + 32*k];
#pragma unroll
        for (int off = 16; off; off >>= 1) a += __shfl_xor_sync(0xffffffffu, a, off);
        if (lane == 0) out[b] = a + hb2[0];
    }
}

// ---------------- launch ----------------
extern "C" void kernel_launch(void* const* d_in, const int* in_sizes, int n_in,
                              void* d_out, int out_size) {
    const float* x        = (const float*)d_in[0];
    const float* w_in     = (const float*)d_in[1];
    const float* b_in     = (const float*)d_in[2];
    const float* ln_in_g  = (const float*)d_in[3];
    const float* ln_in_b  = (const float*)d_in[4];
    const float* s4_B     = (const float*)d_in[5];
    const float* s4_C     = (const float*)d_in[6];
    const float* s4_logdt = (const float*)d_in[7];
    const float* s4_D     = (const float*)d_in[8];
    const float* ln_g     = (const float*)d_in[9];
    const float* ln_b     = (const float*)d_in[10];
    const float* cls      = (const float*)d_in[11];
    const float* mha_in_w = (const float*)d_in[12];
    const float* mha_in_b = (const float*)d_in[13];
    const float* mha_out_w= (const float*)d_in[14];
    const float* mha_out_b= (const float*)d_in[15];
    const float* head_w1  = (const float*)d_in[16];
    const float* head_b1  = (const float*)d_in[17];
    const float* head_w2  = (const float*)d_in[18];
    const float* head_b2  = (const float*)d_in[19];
    float* out = (float*)d_out;

    setup_kernel<<<256, 256>>>(w_in);
    compute_Ad_kernel<<<NL, 512>>>(s4_logdt);
    s4_scan_kernel<<<dim3(Dsz, NL), 64>>>(s4_B, s4_C);
    fft_k_kernel<<<dim3(Dsz/2, NL), 256>>>();
    in_proj_kernel<<<dim3(Bsz, 50), 256>>>(x, b_in);
    ln_pos_norm_t_kernel<<<dim3(Bsz, 32), 256>>>(ln_in_g, ln_in_b);
    for (int layer = 0; layer < NL; layer++) {
        fft_conv_kernel<<<dim3(Bsz, Dsz/2), 256>>>(layer, s4_D);
        post_ln_norm_t_kernel<<<dim3(Bsz, 32), 256>>>(layer, (layer == NL-1) ? 1 : 0, ln_g, ln_b);
    }
    pool_head_kernel<<<Bsz, 256>>>(cls, mha_in_w, mha_in_b, mha_out_w, mha_out_b,
                                   head_w1, head_b1, head_w2, head_b2, out);
}

// round 11
// speedup vs baseline: 1.3352x; 1.1927x over previous
#include <cuda_runtime.h>
#include <cuda_bf16.h>
#include <math.h>

#define Bsz 32
#define Csz 129
#define Tsz 1000
#define Dsz 256
#define Nst 64
#define NL  4
#define FFTN 2048

// ---------------- scratch (device globals; no runtime alloc) ----------------
__device__ float  d_h [Bsz*Tsz*Dsz];     // final hidden (B,T,D) for pooling
__device__ float  d_xt2[Bsz*Tsz*Dsz];    // (B,D,T): normalized x OR conv z, in-place
__device__ float  d_nrm[Bsz*Tsz];        // per (b,t) L2 norm of LN output
__device__ float  d_k [NL*Dsz*Tsz];      // S4 kernels
__device__ float2 d_kf[NL*Dsz*FFTN];     // spectra of kernels
__device__ float  d_Ad[NL*Nst*Nst];
__device__ float  d_E [NL*Nst*Nst];      // Ad^8
__device__ float  d_W [NL*Dsz*8*Nst];    // w_j = (Ad^T)^j b, per (layer,d)
__device__ float  d_twr[256];
__device__ float  d_twi[256];
__device__ float  d_wt[Csz*Dsz];         // transposed w_in
__device__ float  d_pe[Tsz*Dsz];         // positional encoding table

#define PI_D 3.14159265358979323846

// ---------------- complex helpers ----------------
struct C2 { float x, y; };
__device__ __forceinline__ C2 cmul(C2 a, C2 b){ C2 r; r.x = a.x*b.x - a.y*b.y; r.y = a.x*b.y + a.y*b.x; return r; }
__device__ __forceinline__ C2 cadd(C2 a, C2 b){ C2 r; r.x = a.x+b.x; r.y = a.y+b.y; return r; }
__device__ __forceinline__ C2 csub(C2 a, C2 b){ C2 r; r.x = a.x-b.x; r.y = a.y-b.y; return r; }
__device__ __forceinline__ C2 cmulni(C2 a){ C2 r; r.x = a.y; r.y = -a.x; return r; }  // a * (-i)

#define PD(i) ((i) + ((i)>>5))

// ---------------- f32x2 packed fma ----------------
__device__ __forceinline__ unsigned long long fma2(unsigned long long a, unsigned long long b, unsigned long long c){
    unsigned long long d;
    asm("fma.rn.f32x2 %0, %1, %2, %3;" : "=l"(d) : "l"(a), "l"(b), "l"(c));
    return d;
}
__device__ __forceinline__ float2 unpack2(unsigned long long v){
    float2 r; asm("mov.b64 {%0, %1}, %2;" : "=f"(r.x), "=f"(r.y) : "l"(v)); return r;
}

// ---------------- setup: twiddles, w transpose, pos-encoding ----------------
__global__ void setup_kernel(const float* __restrict__ w_in) {
    int idx = blockIdx.x * blockDim.x + threadIdx.x;
    int stride = gridDim.x * blockDim.x;
    if (idx < 256) {
        double ang = -2.0 * PI_D * (double)idx / (double)FFTN;
        d_twr[idx] = (float)cos(ang);
        d_twi[idx] = (float)sin(ang);
    }
    for (int i = idx; i < Csz*Dsz; i += stride) {
        int dd = i / Csz, c = i % Csz;
        d_wt[c*Dsz + dd] = w_in[i];
    }
    for (int i = idx; i < Tsz*Dsz; i += stride) {
        int t = i / Dsz, dd = i % Dsz;
        double divv = exp(-(double)(dd >> 1) * 2.0 * log(10000.0) / (double)Dsz);
        double arg = (double)t * divv;
        d_pe[i] = (float)((dd & 1) ? cos(arg) : sin(arg));
    }
}

// ---------------- Ad = solve(I - dtA, I + dtA): pivot-free Gauss-Jordan -----
__global__ void compute_Ad_kernel(const float* __restrict__ s4_logdt) {
    int layer = blockIdx.x;
    __shared__ float M[64][65];
    __shared__ float R[64][65];
    __shared__ float fcol[64];
    __shared__ float rkM[64];
    __shared__ float rkR[64];
    int tid = threadIdx.x; // 512 threads

    float logdt = s4_logdt[layer*Dsz + 0];
    float dt = fminf(fmaxf(expf(logdt), 1e-4f), 0.1f);
    float hdt = dt * 0.5f;

    for (int idx = tid; idx < 64*64; idx += 512) {
        int i = idx >> 6, j = idx & 63;
        float Pi = sqrtf(1.0f + 2.0f*i), Pj = sqrtf(1.0f + 2.0f*j);
        float a;
        if (i == j)      a = -((float)i + 0.5f);
        else if (i > j)  a = -Pi*Pj;
        else             a =  Pi*Pj;
        float eye = (i == j) ? 1.0f : 0.0f;
        M[i][j] = eye - hdt*a;
        R[i][j] = eye + hdt*a;
    }
    __syncthreads();

    for (int k = 0; k < 64; k++) {
        float ipv = 1.0f / M[k][k];
        if (tid < 64) {
            fcol[tid] = (tid == k) ? 0.0f : M[tid][k] * ipv;
        } else if (tid < 128) {
            int c = tid - 64; rkM[c] = M[k][c];
        } else if (tid < 192) {
            int c = tid - 128; rkR[c] = R[k][c];
        }
        __syncthreads();
#pragma unroll
        for (int it = 0; it < 16; it++) {
            int e = tid + 512*it;
            int mat = e >> 12;
            int idx = e & 4095;
            int i = idx >> 6, j = idx & 63;
            if (mat == 0) {
                M[i][j] = (i == k) ? rkM[j]*ipv : M[i][j] - fcol[i]*rkM[j];
            } else {
                R[i][j] = (i == k) ? rkR[j]*ipv : R[i][j] - fcol[i]*rkR[j];
            }
        }
        __syncthreads();
    }
    for (int idx = tid; idx < 64*64; idx += 512)
        d_Ad[layer*4096 + idx] = R[idx >> 6][idx & 63];
}

// ---------------- E = Ad^8 via 3 squarings ----------------
__global__ void s4_E_kernel() {
    int layer = blockIdx.x;
    int tid = threadIdx.x;  // 512
    __shared__ float A[64][65], Bm[64][65];
    for (int idx = tid; idx < 4096; idx += 512)
        A[idx >> 6][idx & 63] = d_Ad[layer*4096 + idx];
    __syncthreads();
    for (int rep = 0; rep < 3; rep++) {
        for (int idx = tid; idx < 4096; idx += 512) {
            int i = idx >> 6, j = idx & 63;
            float acc = 0.f;
#pragma unroll 8
            for (int k = 0; k < 64; k++) acc += A[i][k]*A[k][j];
            Bm[i][j] = acc;
        }
        __syncthreads();
        for (int idx = tid; idx < 4096; idx += 512)
            A[idx >> 6][idx & 63] = Bm[idx >> 6][idx & 63];
        __syncthreads();
    }
    for (int idx = tid; idx < 4096; idx += 512)
        d_E[layer*4096 + idx] = A[idx >> 6][idx & 63];
}

// ---------------- W: w_0 = b; w_{j+1} = Ad^T w_j ----------------
__global__ void s4_W_kernel(const float* __restrict__ s4_B) {
    int d = blockIdx.x, layer = blockIdx.y;
    int n = threadIdx.x;  // 64
    __shared__ float wj[64];
    float adT[64];
#pragma unroll
    for (int m = 0; m < 64; m++) adT[m] = d_Ad[layer*4096 + m*64 + n];
    float w = s4_B[(layer*Nst + n)*Dsz + d];
    float* Wp = d_W + ((size_t)(layer*Dsz + d))*512;
    Wp[n] = w;
    for (int j = 1; j < 8; j++) {
        wj[n] = w;
        __syncthreads();
        float acc = 0.f;
#pragma unroll
        for (int m = 0; m < 64; m++) acc += adT[m]*wj[m];
        w = acc;
        Wp[j*64 + n] = w;
        __syncthreads();
    }
}

// ------- S4 recurrence -> d_k: 8 outputs per iteration via E = Ad^8 --------
// Clamps in the reference are provably inactive (contractive Cayley step,
// ||x_0|| ~ 0.6), so the recurrence is linear and we hop 8 steps at a time.
__global__ void s4_scan_kernel(const float* __restrict__ s4_C) {
    int d = blockIdx.x, layer = blockIdx.y;
    int n = threadIdx.x;               // 64 threads
    __shared__ __align__(8) float xs[2][64];
    __shared__ float stage[2][64][9];
    unsigned long long e2[32];
    const float* Ep = d_E + layer*4096 + n*64;
#pragma unroll
    for (int j = 0; j < 32; j++) {
        float lo = Ep[2*j], hi = Ep[2*j+1];
        unsigned long long v;
        asm("mov.b64 %0, {%1, %2};" : "=l"(v) : "f"(lo), "f"(hi));
        e2[j] = v;
    }
    float wv[8];
    const float* Wp = d_W + ((size_t)(layer*Dsz + d))*512;
#pragma unroll
    for (int j = 0; j < 8; j++) wv[j] = Wp[j*64 + n];
    xs[0][n] = s4_C[(layer*Dsz + d)*Nst + n];
    __syncthreads();
    float* kp = d_k + (layer*Dsz + d)*Tsz;
    int g8 = n >> 3, j8 = n & 7;
    int cur = 0;
    for (int it = 0; it < 125; it++) {
        float x = xs[cur][n];
        int buf = it & 1;
#pragma unroll
        for (int j = 0; j < 8; j++) stage[buf][n][j] = x * wv[j];
        const unsigned long long* xv = reinterpret_cast<const unsigned long long*>(&xs[cur][0]);
        unsigned long long a0 = 0ULL, a1 = 0ULL, a2 = 0ULL, a3 = 0ULL;
#pragma unroll
        for (int j = 0; j < 8; j++) {
            a0 = fma2(e2[j],      xv[j],      a0);
            a1 = fma2(e2[j + 8],  xv[j + 8],  a1);
            a2 = fma2(e2[j + 16], xv[j + 16], a2);
            a3 = fma2(e2[j + 24], xv[j + 24], a3);
        }
        float2 f0 = unpack2(a0), f1 = unpack2(a1), f2 = unpack2(a2), f3 = unpack2(a3);
        float acc = ((f0.x + f0.y) + (f1.x + f1.y)) + ((f2.x + f2.y) + (f3.x + f3.y));
        xs[cur ^ 1][n] = fminf(fmaxf(acc, -100.0f), 100.0f);
        __syncthreads();
        // group g8 reduces output t = it*8 + g8
        float s = 0.f;
#pragma unroll
        for (int m = 0; m < 8; m++) s += stage[buf][j8 + 8*m][g8];
        s += __shfl_xor_sync(0xffffffffu, s, 4);
        s += __shfl_xor_sync(0xffffffffu, s, 2);
        s += __shfl_xor_sync(0xffffffffu, s, 1);
        if (j8 == 0) {
            int tt = it*8 + g8;
            float ks = fminf(fmaxf(s, -10.0f), 10.0f);
            kp[tt] = ks * expf(-0.01f * (float)tt);
        }
        cur ^= 1;
    }
}

// ---------------- radix-8 butterfly with twiddle ----------------
__device__ __forceinline__ void bf8(C2* v, C2 w1) {
    C2 t0 = cadd(v[0], v[4]), t1 = csub(v[0], v[4]);
    C2 t2 = cadd(v[2], v[6]), t3 = cmulni(csub(v[2], v[6]));
    C2 e0 = cadd(t0, t2), e1 = cadd(t1, t3), e2 = csub(t0, t2), e3 = csub(t1, t3);
    C2 u0 = cadd(v[1], v[5]), u1 = csub(v[1], v[5]);
    C2 u2 = cadd(v[3], v[7]), u3 = cmulni(csub(v[3], v[7]));
    C2 o0 = cadd(u0, u2), o1 = cadd(u1, u3), o2 = csub(u0, u2), o3 = csub(u1, u3);
    const float c = 0.70710678118654752440f;
    C2 q1; q1.x = c*(o1.x + o1.y); q1.y = c*(o1.y - o1.x);
    C2 q2 = cmulni(o2);
    C2 q3; q3.x = c*(o3.y - o3.x); q3.y = -c*(o3.x + o3.y);
    v[0] = cadd(e0, o0); v[1] = cadd(e1, q1); v[2] = cadd(e2, q2); v[3] = cadd(e3, q3);
    v[4] = csub(e0, o0); v[5] = csub(e1, q1); v[6] = csub(e2, q2); v[7] = csub(e3, q3);
    C2 w2 = cmul(w1, w1), w3 = cmul(w2, w1), w4 = cmul(w2, w2);
    C2 w5 = cmul(w4, w1), w6 = cmul(w4, w2), w7 = cmul(w4, w3);
    v[1] = cmul(v[1], w1); v[2] = cmul(v[2], w2); v[3] = cmul(v[3], w3);
    v[4] = cmul(v[4], w4); v[5] = cmul(v[5], w5); v[6] = cmul(v[6], w6); v[7] = cmul(v[7], w7);
}

// one Stockham radix-8 stage: reads src at q+s*p (+256k), writes dst at q+8sp (+sk)
__device__ __forceinline__ void stage8(const float* sr, const float* si,
                                       float* dr, float* di,
                                       const float* twr, const float* twi,
                                       int p, int q, int s) {
    C2 v[8];
    int base = q + s*p;
#pragma unroll
    for (int k = 0; k < 8; k++) {
        int ix = PD(base + 256*k);
        v[k].x = sr[ix]; v[k].y = si[ix];
    }
    int j = PD(p*s);
    C2 w1; w1.x = twr[j]; w1.y = twi[j];
    bf8(v, w1);
    int wb = q + 8*s*p;
#pragma unroll
    for (int k = 0; k < 8; k++) {
        int ix = PD(wb + s*k);
        dr[ix] = v[k].x; di[ix] = v[k].y;
    }
}

// full 2048 FFT: input AND result in (pr, pi); (qr, qi) is scratch. 256 threads.
__device__ __forceinline__ void fft2048s(float* pr, float* pi, float* qr, float* qi,
                                         const float* twr, const float* twi) {
    int tid = threadIdx.x;
    __syncthreads();   // input visible
    stage8(pr, pi, qr, qi, twr, twi, tid, 0, 1);             // n=2048, s=1
    __syncthreads();
    stage8(qr, qi, pr, pi, twr, twi, tid & 31, tid >> 5, 8); // n=256, s=8
    __syncthreads();
    stage8(pr, pi, qr, qi, twr, twi, tid >> 6, tid & 63, 64);// n=32, s=64
    __syncthreads();
#pragma unroll
    for (int h = 0; h < 2; h++) {
        int q = tid + 256*h;
        C2 x0; x0.x = qr[PD(q)];        x0.y = qi[PD(q)];
        C2 x1; x1.x = qr[PD(q + 512)];  x1.y = qi[PD(q + 512)];
        C2 x2; x2.x = qr[PD(q + 1024)]; x2.y = qi[PD(q + 1024)];
        C2 x3; x3.x = qr[PD(q + 1536)]; x3.y = qi[PD(q + 1536)];
        C2 t0 = cadd(x0, x2), t1 = csub(x0, x2);
        C2 t2 = cadd(x1, x3), t3 = cmulni(csub(x1, x3));
        int o0 = PD(q), o1 = PD(q + 512), o2 = PD(q + 1024), o3 = PD(q + 1536);
        pr[o0] = t0.x + t2.x; pi[o0] = t0.y + t2.y;
        pr[o1] = t1.x + t3.x; pi[o1] = t1.y + t3.y;
        pr[o2] = t0.x - t2.x; pi[o2] = t0.y - t2.y;
        pr[o3] = t1.x - t3.x; pi[o3] = t1.y - t3.y;
    }
    __syncthreads();   // result visible
}

// ---------------- kernel spectra: pack 2 d's per FFT ----------------
__global__ void fft_k_kernel() {
    __shared__ float ar[2112], ai[2112], br[2112], bi[2112];
    __shared__ float twr_s[264], twi_s[264];
    int tid = threadIdx.x;
    int dp = blockIdx.x, layer = blockIdx.y;
    int d0 = dp*2, d1 = dp*2 + 1;
    twr_s[PD(tid)] = d_twr[tid];
    twi_s[PD(tid)] = d_twi[tid];
    const float* k0 = d_k + (layer*Dsz + d0)*Tsz;
    const float* k1 = d_k + (layer*Dsz + d1)*Tsz;
#pragma unroll
    for (int q = 0; q < 8; q++) {
        int t = tid + 256*q;
        float v0 = (t < Tsz) ? k0[t] : 0.0f;
        float v1 = (t < Tsz) ? k1[t] : 0.0f;
        ar[PD(t)] = v0; ai[PD(t)] = v1;
    }
    fft2048s(ar, ai, br, bi, twr_s, twi_s);
    float2* K0 = d_kf + (layer*Dsz + d0)*FFTN;
    float2* K1 = d_kf + (layer*Dsz + d1)*FFTN;
#pragma unroll
    for (int q = 0; q < 8; q++) {
        int f = tid + 256*q;
        int fm = (FFTN - f) & (FFTN - 1);
        C2 Zf; Zf.x = ar[PD(f)];  Zf.y = ai[PD(f)];
        C2 Zm; Zm.x = ar[PD(fm)]; Zm.y = ai[PD(fm)];
        K0[f] = make_float2(0.5f*(Zf.x + Zm.x), 0.5f*(Zf.y - Zm.y));
        K1[f] = make_float2(0.5f*(Zf.y + Zm.y), 0.5f*(Zm.x - Zf.x));
    }
}

// ---- input projection + LN + pos-enc + L2-normalize -> d_xt2 (B,D,T) -------
__global__ void in_proj_ln_kernel(const float* __restrict__ x,
                                  const float* __restrict__ b_in,
                                  const float* __restrict__ g,
                                  const float* __restrict__ bbp) {
    int b = blockIdx.x, t0 = blockIdx.y * 20;
    int tid = threadIdx.x;          // tid = d
    int lane = tid & 31, w = tid >> 5;
    __shared__ float ws[32][256];
    __shared__ float xs[32][20];
    __shared__ float red1[8][20], red2[8][20];
    __shared__ float msh[20], ish[20];
    float acc[20];
#pragma unroll
    for (int j = 0; j < 20; j++) acc[j] = 0.0f;
    for (int c0 = 0; c0 < Csz; c0 += 32) {
        __syncthreads();
#pragma unroll
        for (int i = 0; i < 32; i++)
            ws[i][tid] = (c0 + i < Csz) ? d_wt[(c0 + i)*Dsz + tid] : 0.0f;
        for (int l = tid; l < 640; l += 256) {
            int cc = l / 20, j = l % 20;
            xs[cc][j] = (c0 + cc < Csz) ? x[(b*Csz + c0 + cc)*Tsz + t0 + j] : 0.0f;
        }
        __syncthreads();
#pragma unroll
        for (int cc = 0; cc < 32; cc++) {
            float wv = ws[cc][tid];
#pragma unroll
            for (int j = 0; j < 20; j++) acc[j] += wv * xs[cc][j];
        }
    }
    float bias = b_in[tid];
#pragma unroll
    for (int j = 0; j < 20; j++) acc[j] += bias;
    // block reduction 1: mean / var per t
#pragma unroll
    for (int j = 0; j < 20; j++) {
        float sv = acc[j], sq = acc[j]*acc[j];
#pragma unroll
        for (int off = 16; off; off >>= 1) {
            sv += __shfl_xor_sync(0xffffffffu, sv, off);
            sq += __shfl_xor_sync(0xffffffffu, sq, off);
        }
        if (lane == 0) { red1[w][j] = sv; red2[w][j] = sq; }
    }
    __syncthreads();
    if (tid < 20) {
        float S = 0.f, Q = 0.f;
        for (int ww = 0; ww < 8; ww++) { S += red1[ww][tid]; Q += red2[ww][tid]; }
        float m = S * (1.0f/256.0f);
        float var = Q * (1.0f/256.0f) - m*m;
        msh[tid] = m; ish[tid] = rsqrtf(var + 1e-5f);
    }
    __syncthreads();
    float gv = g[tid], bv = bbp[tid];
    float o[20];
#pragma unroll
    for (int j = 0; j < 20; j++)
        o[j] = (acc[j] - msh[j])*ish[j]*gv + bv + d_pe[(t0 + j)*Dsz + tid];
    // block reduction 2: L2 norm per t
#pragma unroll
    for (int j = 0; j < 20; j++) {
        float sq = o[j]*o[j];
#pragma unroll
        for (int off = 16; off; off >>= 1)
            sq += __shfl_xor_sync(0xffffffffu, sq, off);
        if (lane == 0) red1[w][j] = sq;
    }
    __syncthreads();
    if (tid < 20) {
        float Q = 0.f;
        for (int ww = 0; ww < 8; ww++) Q += red1[ww][tid];
        float nrm = sqrtf(Q) + 1e-8f;
        d_nrm[b*Tsz + t0 + tid] = nrm;
        ish[tid] = 1.0f / nrm;    // reuse as inv-norm
    }
    __syncthreads();
#pragma unroll
    for (int j = 0; j < 20; j++) o[j] *= ish[j];
    float* op = d_xt2 + ((size_t)b*Dsz + tid)*Tsz + t0;
    float4* op4 = reinterpret_cast<float4*>(op);
#pragma unroll
    for (int q = 0; q < 5; q++)
        op4[q] = make_float4(o[4*q], o[4*q+1], o[4*q+2], o[4*q+3]);
}

// -------- FFT conv + gate + gelu + residual (z = gelu(y)+1.1h), in-place ----
__global__ void fft_conv_kernel(int layer, const float* __restrict__ s4_D) {
    __shared__ float ar[2112], ai[2112], br[2112], bi[2112];
    __shared__ float twr_s[264], twi_s[264];
    int tid = threadIdx.x;
    int b = blockIdx.x, dp = blockIdx.y;
    int d0 = dp*2, d1 = dp*2 + 1;
    twr_s[PD(tid)] = d_twr[tid];
    twi_s[PD(tid)] = d_twi[tid];
    float* x0 = d_xt2 + ((size_t)b*Dsz + d0)*Tsz;
    float* x1 = d_xt2 + ((size_t)b*Dsz + d1)*Tsz;
    const float* np = d_nrm + b*Tsz;
    float xr0[4], xr1[4], nr[4];
#pragma unroll
    for (int q = 0; q < 8; q++) {
        int t = tid + 256*q;
        float v0 = 0.0f, v1 = 0.0f;
        if (t < Tsz) { v0 = x0[t]; v1 = x1[t]; }
        if (q < 4) {
            xr0[q] = v0; xr1[q] = v1;
            nr[q] = (t < Tsz) ? np[t] : 0.0f;
        }
        ar[PD(t)] = v0; ai[PD(t)] = v1;
    }
    fft2048s(ar, ai, br, bi, twr_s, twi_s);   // Z in ar/ai
    const float2* K0 = d_kf + (layer*Dsz + d0)*FFTN;
    const float2* K1 = d_kf + (layer*Dsz + d1)*FFTN;
#pragma unroll
    for (int q = 0; q < 8; q++) {
        int f = tid + 256*q;
        int fm = (FFTN - f) & (FFTN - 1);
        C2 Zf; Zf.x = ar[PD(f)];  Zf.y = ai[PD(f)];
        C2 Zm; Zm.x = ar[PD(fm)]; Zm.y = ai[PD(fm)];
        C2 X0; X0.x = 0.5f*(Zf.x + Zm.x); X0.y = 0.5f*(Zf.y - Zm.y);
        C2 X1; X1.x = 0.5f*(Zf.y + Zm.y); X1.y = 0.5f*(Zm.x - Zf.x);
        float2 k0 = K0[f], k1 = K1[f];
        C2 c0; c0.x = k0.x; c0.y = k0.y;
        C2 c1; c1.x = k1.x; c1.y = k1.y;
        C2 Y0 = cmul(X0, c0);
        C2 Y1 = cmul(X1, c1);
        br[PD(f)] = Y0.x - Y1.y;           // conj(S), S = Y0 + i*Y1
        bi[PD(f)] = -(Y0.y + Y1.x);
    }
    fft2048s(br, bi, ar, ai, twr_s, twi_s);   // V in br/bi; ifft = conj(V)/N
    float gate0 = 1.0f / (1.0f + expf(-s4_D[layer*Dsz + d0]));
    float gate1 = 1.0f / (1.0f + expf(-s4_D[layer*Dsz + d1]));
    const float inv = 1.0f / (float)FFTN;
#pragma unroll
    for (int q = 0; q < 4; q++) {
        int t = tid + 256*q;
        if (t < Tsz) {
            float y0 =  br[PD(t)]*inv + xr0[q]*gate0;
            float y1 = -bi[PD(t)]*inv + xr1[q]*gate1;
            float gl0 = 0.5f*y0*(1.0f + erff(y0*0.70710678118654752f));
            float gl1 = 0.5f*y1*(1.0f + erff(y1*0.70710678118654752f));
            x0[t] = gl0 + 1.1f*xr0[q]*nr[q];   // z = gelu(y) + 1.1*h
            x1[t] = gl1 + 1.1f*xr1[q]*nr[q];
        }
    }
}

// ---- post: LN(z); last -> d_h (B,T,D); else normalized transposed + norms --
__global__ void post_ln_norm_t_kernel(int layer, int last,
                                      const float* __restrict__ ln_g,
                                      const float* __restrict__ ln_b) {
    __shared__ float tile[32][257];
    int b = blockIdx.x, t0 = blockIdx.y * 32;
    int tid = threadIdx.x, lane = tid & 31, w = tid >> 5;
#pragma unroll
    for (int i = 0; i < 32; i++) {
        int dd = i*8 + w;
        int t = t0 + lane;
        tile[lane][dd] = (t < Tsz) ? d_xt2[((size_t)b*Dsz + dd)*Tsz + t] : 0.0f;
    }
    __syncthreads();
    const float* g  = ln_g + layer*Dsz;
    const float* bb = ln_b + layer*Dsz;
#pragma unroll
    for (int j = 0; j < 4; j++) {
        int r = w + 8*j;
        int t = t0 + r;
        if (t >= Tsz) continue;
        float z[8]; float s = 0.f, s2 = 0.f;
#pragma unroll
        for (int k = 0; k < 8; k++) {
            float zz = tile[r][lane + 32*k];
            z[k] = zz; s += zz; s2 += zz*zz;
        }
#pragma unroll
        for (int off = 16; off; off >>= 1) {
            s  += __shfl_xor_sync(0xffffffffu, s,  off);
            s2 += __shfl_xor_sync(0xffffffffu, s2, off);
        }
        float m = s * (1.0f/256.0f);
        float var = s2 * (1.0f/256.0f) - m*m;
        float is = rsqrtf(var + 1e-5f);
        if (last) {
            float* hp = d_h + ((size_t)b*Tsz + t)*Dsz;
#pragma unroll
            for (int k = 0; k < 8; k++) {
                int dd = lane + 32*k;
                hp[dd] = (z[k] - m)*is*g[dd] + bb[dd];
            }
        } else {
            float o[8]; float ss = 0.f;
#pragma unroll
            for (int k = 0; k < 8; k++) {
                int dd = lane + 32*k;
                float ov = (z[k] - m)*is*g[dd] + bb[dd];
                o[k] = ov; ss += ov*ov;
            }
#pragma unroll
            for (int off = 16; off; off >>= 1) ss += __shfl_xor_sync(0xffffffffu, ss, off);
            float nrm = sqrtf(ss) + 1e-8f;
            float invn = 1.0f / nrm;
            if (lane == 0) d_nrm[b*Tsz + t] = nrm;
#pragma unroll
            for (int k = 0; k < 8; k++) tile[r][lane + 32*k] = o[k]*invn;
        }
    }
    if (last) return;
    __syncthreads();
#pragma unroll
    for (int i = 0; i < 32; i++) {
        int dd = i*8 + w;
        int t = t0 + lane;
        if (t < Tsz) d_xt2[((size_t)b*Dsz + dd)*Tsz + t] = tile[lane][dd];
    }
}

// ---------------- fused MHA pooling + head ----------------
__global__ void pool_head_kernel(const float* __restrict__ cls,
                                 const float* __restrict__ in_w,
                                 const float* __restrict__ in_b,
                                 const float* __restrict__ out_w,
                                 const float* __restrict__ out_b,
                                 const float* __restrict__ hw1,
                                 const float* __restrict__ hb1,
                                 const float* __restrict__ hw2,
                                 const float* __restrict__ hb2,
                                 float* __restrict__ out) {
    int b = blockIdx.x;
    int tid = threadIdx.x, lane = tid & 31, w = tid >> 5;
    __shared__ float Q[256];
    __shared__ float vp[8][256];
    __shared__ float sc[8][1001];
    __shared__ float ch[8];
    __shared__ float red[256];
    __shared__ float hsm[128];

    {
        float acc = in_b[tid];
        for (int c = 0; c < 256; c++) acc += cls[c] * in_w[tid*256 + c];
        Q[tid] = acc;
    }
    __syncthreads();
#pragma unroll
    for (int h = 0; h < 8; h++) {
        float acc = 0.f;
#pragma unroll
        for (int i = 0; i < 32; i++)
            acc += in_w[(256 + h*32 + i)*256 + tid] * Q[h*32 + i];
        vp[h][tid] = acc;
    }
    if (tid < 8) {
        float acc = 0.f;
        for (int i = 0; i < 32; i++) acc += in_b[256 + tid*32 + i] * Q[tid*32 + i];
        ch[tid] = acc;
    }
    __syncthreads();
    const float iss = 0.17677669529663687f; // 1/sqrt(32)
    for (int s = w; s < 1001; s += 8) {
        const float* kvr = (s == 0) ? cls : (d_h + ((size_t)b*Tsz + s - 1)*Dsz);
        float xv[8];
#pragma unroll
        for (int k = 0; k < 8; k++) xv[k] = kvr[lane*8 + k];
#pragma unroll
        for (int h = 0; h < 8; h++) {
            float a = 0.f;
#pragma unroll
            for (int k = 0; k < 8; k++) a += xv[k] * vp[h][lane*8 + k];
#pragma unroll
            for (int off = 16; off; off >>= 1) a += __shfl_xor_sync(0xffffffffu, a, off);
            if (lane == h) sc[h][s] = (a + ch[h]) * iss;
        }
    }
    __syncthreads();
    {
        int h = w;
        float mx = -1e30f;
        for (int s = lane; s < 1001; s += 32) mx = fmaxf(mx, sc[h][s]);
#pragma unroll
        for (int off = 16; off; off >>= 1) mx = fmaxf(mx, __shfl_xor_sync(0xffffffffu, mx, off));
        float sum = 0.f;
        for (int s = lane; s < 1001; s += 32) { float e = expf(sc[h][s] - mx); sc[h][s] = e; sum += e; }
#pragma unroll
        for (int off = 16; off; off >>= 1) sum += __shfl_xor_sync(0xffffffffu, sum, off);
        float invs = 1.0f / sum;
        for (int s = lane; s < 1001; s += 32) sc[h][s] *= invs;
    }
    __syncthreads();
    float pj[8];
#pragma unroll
    for (int h = 0; h < 8; h++) pj[h] = 0.f;
    for (int s = 0; s < 1001; s++) {
        float kvv = (s == 0) ? cls[tid] : d_h[((size_t)b*Tsz + s - 1)*Dsz + tid];
#pragma unroll
        for (int h = 0; h < 8; h++) pj[h] += sc[h][s] * kvv;
    }
    __syncthreads();
#pragma unroll
    for (int h = 0; h < 8; h++) vp[h][tid] = pj[h];
    __syncthreads();
    {
        int h = tid >> 5;
        float acc = in_b[512 + tid];
        for (int j = 0; j < 256; j++) acc += in_w[(512 + tid)*256 + j] * vp[h][j];
        Q[tid] = acc;
    }
    __syncthreads();
    {
        float acc = out_b[tid];
        for (int i = 0; i < 256; i++) acc += out_w[tid*256 + i] * Q[i];
        red[tid] = acc;
    }
    __syncthreads();
    if (tid < 128) {
        float acc = hb1[tid];
        for (int i = 0; i < 256; i++) acc += hw1[tid*256 + i] * red[i];
        hsm[tid] = fmaxf(acc, 0.0f);
    }
    __syncthreads();
    if (w == 0) {
        float a = 0.f;
#pragma unroll
        for (int k = 0; k < 4; k++) a += hsm[lane + 32*k] * hw2[lane + 32*k];
#pragma unroll
        for (int off = 16; off; off >>= 1) a += __shfl_xor_sync(0xffffffffu, a, off);
        if (lane == 0) out[b] = a + hb2[0];
    }
}

// ---------------- launch ----------------
extern "C" void kernel_launch(void* const* d_in, const int* in_sizes, int n_in,
                              void* d_out, int out_size) {
    const float* x        = (const float*)d_in[0];
    const float* w_in     = (const float*)d_in[1];
    const float* b_in     = (const float*)d_in[2];
    const float* ln_in_g  = (const float*)d_in[3];
    const float* ln_in_b  = (const float*)d_in[4];
    const float* s4_B     = (const float*)d_in[5];
    const float* s4_C     = (const float*)d_in[6];
    const float* s4_logdt = (const float*)d_in[7];
    const float* s4_D     = (const float*)d_in[8];
    const float* ln_g     = (const float*)d_in[9];
    const float* ln_b     = (const float*)d_in[10];
    const float* cls      = (const float*)d_in[11];
    const float* mha_in_w = (const float*)d_in[12];
    const float* mha_in_b = (const float*)d_in[13];
    const float* mha_out_w= (const float*)d_in[14];
    const float* mha_out_b= (const float*)d_in[15];
    const float* head_w1  = (const float*)d_in[16];
    const float* head_b1  = (const float*)d_in[17];
    const float* head_w2  = (const float*)d_in[18];
    const float* head_b2  = (const float*)d_in[19];
    float* out = (float*)d_out;

    setup_kernel<<<256, 256>>>(w_in);
    compute_Ad_kernel<<<NL, 512>>>(s4_logdt);
    s4_E_kernel<<<NL, 512>>>();
    s4_W_kernel<<<dim3(Dsz, NL), 64>>>(s4_B);
    s4_scan_kernel<<<dim3(Dsz, NL), 64>>>(s4_C);
    fft_k_kernel<<<dim3(Dsz/2, NL), 256>>>();
    in_proj_ln_kernel<<<dim3(Bsz, 50), 256>>>(x, b_in, ln_in_g, ln_in_b);
    for (int layer = 0; layer < NL; layer++) {
        fft_conv_kernel<<<dim3(Bsz, Dsz/2), 256>>>(layer, s4_D);
        post_ln_norm_t_kernel<<<dim3(Bsz, 32), 256>>>(layer, (layer == NL-1) ? 1 : 0, ln_g, ln_b);
    }
    pool_head_kernel<<<Bsz, 256>>>(cls, mha_in_w, mha_in_b, mha_out_w, mha_out_b,
                                   head_w1, head_b1, head_w2, head_b2, out);
}

// round 12
// speedup vs baseline: 1.3954x; 1.0451x over previous
#include <cuda_runtime.h>
#include <cuda_bf16.h>
#include <math.h>

#define Bsz 32
#define Csz 129
#define Tsz 1000
#define Dsz 256
#define Nst 64
#define NL  4
#define FFTN 2048

// ---------------- scratch (device globals; no runtime alloc) ----------------
__device__ float  d_h [Bsz*Tsz*Dsz];     // final hidden (B,T,D) for pooling
__device__ float  d_xt2[Bsz*Tsz*Dsz];    // (B,D,T): normalized x OR conv z, in-place
__device__ float  d_nrm[Bsz*Tsz];        // per (b,t) L2 norm of LN output
__device__ float  d_k [NL*Dsz*Tsz];      // S4 kernels
__device__ float2 d_kf[NL*Dsz*FFTN];     // spectra of kernels
__device__ float  d_Ad[NL*Nst*Nst];
__device__ float  d_E [NL*Nst*Nst];      // Ad^8
__device__ float  d_W [NL*Dsz*8*Nst];    // w_j = (Ad^T)^j b, per (layer,d)
__device__ float  d_twr[256];
__device__ float  d_twi[256];
__device__ float  d_wt[Csz*Dsz];         // transposed w_in
__device__ float  d_pe[Tsz*Dsz];         // positional encoding table

#define PI_D 3.14159265358979323846

// ---------------- complex helpers ----------------
struct C2 { float x, y; };
__device__ __forceinline__ C2 cmul(C2 a, C2 b){ C2 r; r.x = a.x*b.x - a.y*b.y; r.y = a.x*b.y + a.y*b.x; return r; }
__device__ __forceinline__ C2 cadd(C2 a, C2 b){ C2 r; r.x = a.x+b.x; r.y = a.y+b.y; return r; }
__device__ __forceinline__ C2 csub(C2 a, C2 b){ C2 r; r.x = a.x-b.x; r.y = a.y-b.y; return r; }
__device__ __forceinline__ C2 cmulni(C2 a){ C2 r; r.x = a.y; r.y = -a.x; return r; }  // a * (-i)

// padded complex (float2) smem index: conflict-free for strides 1/8/64
#define PDC(i) ((i) + ((i)>>4) + ((i)>>8))
#define CBUF 2200

// ---------------- f32x2 packed fma ----------------
__device__ __forceinline__ unsigned long long fma2(unsigned long long a, unsigned long long b, unsigned long long c){
    unsigned long long d;
    asm("fma.rn.f32x2 %0, %1, %2, %3;" : "=l"(d) : "l"(a), "l"(b), "l"(c));
    return d;
}
__device__ __forceinline__ float2 unpack2(unsigned long long v){
    float2 r; asm("mov.b64 {%0, %1}, %2;" : "=f"(r.x), "=f"(r.y) : "l"(v)); return r;
}

// ---------------- setup: twiddles, w transpose, pos-encoding ----------------
__global__ void setup_kernel(const float* __restrict__ w_in) {
    int idx = blockIdx.x * blockDim.x + threadIdx.x;
    int stride = gridDim.x * blockDim.x;
    if (idx < 256) {
        double ang = -2.0 * PI_D * (double)idx / (double)FFTN;
        d_twr[idx] = (float)cos(ang);
        d_twi[idx] = (float)sin(ang);
    }
    for (int i = idx; i < Csz*Dsz; i += stride) {
        int dd = i / Csz, c = i % Csz;
        d_wt[c*Dsz + dd] = w_in[i];
    }
    for (int i = idx; i < Tsz*Dsz; i += stride) {
        int t = i / Dsz, dd = i % Dsz;
        double divv = exp(-(double)(dd >> 1) * 2.0 * log(10000.0) / (double)Dsz);
        double arg = (double)t * divv;
        d_pe[i] = (float)((dd & 1) ? cos(arg) : sin(arg));
    }
}

// ---------------- Ad = solve(I - dtA, I + dtA): pivot-free Gauss-Jordan -----
__global__ void compute_Ad_kernel(const float* __restrict__ s4_logdt) {
    int layer = blockIdx.x;
    __shared__ float M[64][65];
    __shared__ float R[64][65];
    __shared__ float fcol[64];
    __shared__ float rkM[64];
    __shared__ float rkR[64];
    int tid = threadIdx.x; // 512 threads

    float logdt = s4_logdt[layer*Dsz + 0];
    float dt = fminf(fmaxf(expf(logdt), 1e-4f), 0.1f);
    float hdt = dt * 0.5f;

    for (int idx = tid; idx < 64*64; idx += 512) {
        int i = idx >> 6, j = idx & 63;
        float Pi = sqrtf(1.0f + 2.0f*i), Pj = sqrtf(1.0f + 2.0f*j);
        float a;
        if (i == j)      a = -((float)i + 0.5f);
        else if (i > j)  a = -Pi*Pj;
        else             a =  Pi*Pj;
        float eye = (i == j) ? 1.0f : 0.0f;
        M[i][j] = eye - hdt*a;
        R[i][j] = eye + hdt*a;
    }
    __syncthreads();

    for (int k = 0; k < 64; k++) {
        float ipv = 1.0f / M[k][k];
        if (tid < 64) {
            fcol[tid] = (tid == k) ? 0.0f : M[tid][k] * ipv;
        } else if (tid < 128) {
            int c = tid - 64; rkM[c] = M[k][c];
        } else if (tid < 192) {
            int c = tid - 128; rkR[c] = R[k][c];
        }
        __syncthreads();
#pragma unroll
        for (int it = 0; it < 16; it++) {
            int e = tid + 512*it;
            int mat = e >> 12;
            int idx = e & 4095;
            int i = idx >> 6, j = idx & 63;
            if (mat == 0) {
                M[i][j] = (i == k) ? rkM[j]*ipv : M[i][j] - fcol[i]*rkM[j];
            } else {
                R[i][j] = (i == k) ? rkR[j]*ipv : R[i][j] - fcol[i]*rkR[j];
            }
        }
        __syncthreads();
    }
    for (int idx = tid; idx < 64*64; idx += 512)
        d_Ad[layer*4096 + idx] = R[idx >> 6][idx & 63];
}

// ---------------- E = Ad^8 via 3 squarings ----------------
__global__ void s4_E_kernel() {
    int layer = blockIdx.x;
    int tid = threadIdx.x;  // 512
    __shared__ float A[64][65], Bm[64][65];
    for (int idx = tid; idx < 4096; idx += 512)
        A[idx >> 6][idx & 63] = d_Ad[layer*4096 + idx];
    __syncthreads();
    for (int rep = 0; rep < 3; rep++) {
        for (int idx = tid; idx < 4096; idx += 512) {
            int i = idx >> 6, j = idx & 63;
            float acc = 0.f;
#pragma unroll 8
            for (int k = 0; k < 64; k++) acc += A[i][k]*A[k][j];
            Bm[i][j] = acc;
        }
        __syncthreads();
        for (int idx = tid; idx < 4096; idx += 512)
            A[idx >> 6][idx & 63] = Bm[idx >> 6][idx & 63];
        __syncthreads();
    }
    for (int idx = tid; idx < 4096; idx += 512)
        d_E[layer*4096 + idx] = A[idx >> 6][idx & 63];
}

// ---------------- W: w_0 = b; w_{j+1} = Ad^T w_j ----------------
__global__ void s4_W_kernel(const float* __restrict__ s4_B) {
    int d = blockIdx.x, layer = blockIdx.y;
    int n = threadIdx.x;  // 64
    __shared__ float wj[64];
    float adT[64];
#pragma unroll
    for (int m = 0; m < 64; m++) adT[m] = d_Ad[layer*4096 + m*64 + n];
    float w = s4_B[(layer*Nst + n)*Dsz + d];
    float* Wp = d_W + ((size_t)(layer*Dsz + d))*512;
    Wp[n] = w;
    for (int j = 1; j < 8; j++) {
        wj[n] = w;
        __syncthreads();
        float acc = 0.f;
#pragma unroll
        for (int m = 0; m < 64; m++) acc += adT[m]*wj[m];
        w = acc;
        Wp[j*64 + n] = w;
        __syncthreads();
    }
}

// ------- S4 recurrence -> d_k: 8 outputs per iteration via E = Ad^8 --------
__global__ void s4_scan_kernel(const float* __restrict__ s4_C) {
    int d = blockIdx.x, layer = blockIdx.y;
    int n = threadIdx.x;               // 64 threads
    __shared__ __align__(8) float xs[2][64];
    __shared__ float stage[2][64][9];
    unsigned long long e2[32];
    const float* Ep = d_E + layer*4096 + n*64;
#pragma unroll
    for (int j = 0; j < 32; j++) {
        float lo = Ep[2*j], hi = Ep[2*j+1];
        unsigned long long v;
        asm("mov.b64 %0, {%1, %2};" : "=l"(v) : "f"(lo), "f"(hi));
        e2[j] = v;
    }
    float wv[8];
    const float* Wp = d_W + ((size_t)(layer*Dsz + d))*512;
#pragma unroll
    for (int j = 0; j < 8; j++) wv[j] = Wp[j*64 + n];
    xs[0][n] = s4_C[(layer*Dsz + d)*Nst + n];
    __syncthreads();
    float* kp = d_k + (layer*Dsz + d)*Tsz;
    int g8 = n >> 3, j8 = n & 7;
    int cur = 0;
    for (int it = 0; it < 125; it++) {
        float x = xs[cur][n];
        int buf = it & 1;
#pragma unroll
        for (int j = 0; j < 8; j++) stage[buf][n][j] = x * wv[j];
        const unsigned long long* xv = reinterpret_cast<const unsigned long long*>(&xs[cur][0]);
        unsigned long long a0 = 0ULL, a1 = 0ULL, a2 = 0ULL, a3 = 0ULL;
#pragma unroll
        for (int j = 0; j < 8; j++) {
            a0 = fma2(e2[j],      xv[j],      a0);
            a1 = fma2(e2[j + 8],  xv[j + 8],  a1);
            a2 = fma2(e2[j + 16], xv[j + 16], a2);
            a3 = fma2(e2[j + 24], xv[j + 24], a3);
        }
        float2 f0 = unpack2(a0), f1 = unpack2(a1), f2 = unpack2(a2), f3 = unpack2(a3);
        float acc = ((f0.x + f0.y) + (f1.x + f1.y)) + ((f2.x + f2.y) + (f3.x + f3.y));
        xs[cur ^ 1][n] = fminf(fmaxf(acc, -100.0f), 100.0f);
        __syncthreads();
        float s = 0.f;
#pragma unroll
        for (int m = 0; m < 8; m++) s += stage[buf][j8 + 8*m][g8];
        s += __shfl_xor_sync(0xffffffffu, s, 4);
        s += __shfl_xor_sync(0xffffffffu, s, 2);
        s += __shfl_xor_sync(0xffffffffu, s, 1);
        if (j8 == 0) {
            int tt = it*8 + g8;
            float ks = fminf(fmaxf(s, -10.0f), 10.0f);
            kp[tt] = ks * expf(-0.01f * (float)tt);
        }
        cur ^= 1;
    }
}

// ---------------- radix-8 butterfly with twiddle ----------------
__device__ __forceinline__ void bf8(C2* v, C2 w1) {
    C2 t0 = cadd(v[0], v[4]), t1 = csub(v[0], v[4]);
    C2 t2 = cadd(v[2], v[6]), t3 = cmulni(csub(v[2], v[6]));
    C2 e0 = cadd(t0, t2), e1 = cadd(t1, t3), e2 = csub(t0, t2), e3 = csub(t1, t3);
    C2 u0 = cadd(v[1], v[5]), u1 = csub(v[1], v[5]);
    C2 u2 = cadd(v[3], v[7]), u3 = cmulni(csub(v[3], v[7]));
    C2 o0 = cadd(u0, u2), o1 = cadd(u1, u3), o2 = csub(u0, u2), o3 = csub(u1, u3);
    const float c = 0.70710678118654752440f;
    C2 q1; q1.x = c*(o1.x + o1.y); q1.y = c*(o1.y - o1.x);
    C2 q2 = cmulni(o2);
    C2 q3; q3.x = c*(o3.y - o3.x); q3.y = -c*(o3.x + o3.y);
    v[0] = cadd(e0, o0); v[1] = cadd(e1, q1); v[2] = cadd(e2, q2); v[3] = cadd(e3, q3);
    v[4] = csub(e0, o0); v[5] = csub(e1, q1); v[6] = csub(e2, q2); v[7] = csub(e3, q3);
    C2 w2 = cmul(w1, w1), w3 = cmul(w2, w1), w4 = cmul(w2, w2);
    C2 w5 = cmul(w4, w1), w6 = cmul(w4, w2), w7 = cmul(w4, w3);
    v[1] = cmul(v[1], w1); v[2] = cmul(v[2], w2); v[3] = cmul(v[3], w3);
    v[4] = cmul(v[4], w4); v[5] = cmul(v[5], w5); v[6] = cmul(v[6], w6); v[7] = cmul(v[7], w7);
}

// one Stockham radix-8 stage on float2 buffers
__device__ __forceinline__ void stage8c(const float2* __restrict__ s, float2* __restrict__ d,
                                        const float2* __restrict__ tw,
                                        int p, int q, int st) {
    C2 v[8];
    int base = q + st*p;
#pragma unroll
    for (int k = 0; k < 8; k++) {
        float2 u = s[PDC(base + 256*k)];
        v[k].x = u.x; v[k].y = u.y;
    }
    float2 tv = tw[PDC(p*st)];
    C2 w1; w1.x = tv.x; w1.y = tv.y;
    bf8(v, w1);
    int wb = q + 8*st*p;
#pragma unroll
    for (int k = 0; k < 8; k++)
        d[PDC(wb + st*k)] = make_float2(v[k].x, v[k].y);
}

// full 2048 FFT on float2 smem: input AND result in P; Q is scratch. 256 thr.
// Identical arithmetic/order to the split-array version.
__device__ __forceinline__ void fft2048c(float2* P, float2* Q,
                                         const float2* __restrict__ tw) {
    int tid = threadIdx.x;
    __syncthreads();   // input visible
    stage8c(P, Q, tw, tid, 0, 1);             // n=2048, s=1
    __syncthreads();
    stage8c(Q, P, tw, tid & 31, tid >> 5, 8); // n=256, s=8
    __syncthreads();
    stage8c(P, Q, tw, tid >> 6, tid & 63, 64);// n=32, s=64
    __syncthreads();
    // radix-4, s=512, no twiddle; 2 butterflies/thread, Q -> P
#pragma unroll
    for (int h = 0; h < 2; h++) {
        int q = tid + 256*h;
        float2 u0 = Q[PDC(q)], u1 = Q[PDC(q + 512)];
        float2 u2 = Q[PDC(q + 1024)], u3 = Q[PDC(q + 1536)];
        C2 x0; x0.x = u0.x; x0.y = u0.y;
        C2 x1; x1.x = u1.x; x1.y = u1.y;
        C2 x2; x2.x = u2.x; x2.y = u2.y;
        C2 x3; x3.x = u3.x; x3.y = u3.y;
        C2 t0 = cadd(x0, x2), t1 = csub(x0, x2);
        C2 t2 = cadd(x1, x3), t3 = cmulni(csub(x1, x3));
        P[PDC(q)]        = make_float2(t0.x + t2.x, t0.y + t2.y);
        P[PDC(q + 512)]  = make_float2(t1.x + t3.x, t1.y + t3.y);
        P[PDC(q + 1024)] = make_float2(t0.x - t2.x, t0.y - t2.y);
        P[PDC(q + 1536)] = make_float2(t1.x - t3.x, t1.y - t3.y);
    }
    __syncthreads();   // result visible
}

// ---------------- kernel spectra: pack 2 d's per FFT ----------------
__global__ void fft_k_kernel() {
    __shared__ float2 A[CBUF], Bc[CBUF];
    __shared__ float2 tws[280];
    int tid = threadIdx.x;
    int dp = blockIdx.x, layer = blockIdx.y;
    int d0 = dp*2, d1 = dp*2 + 1;
    tws[PDC(tid)] = make_float2(d_twr[tid], d_twi[tid]);
    const float* k0 = d_k + (layer*Dsz + d0)*Tsz;
    const float* k1 = d_k + (layer*Dsz + d1)*Tsz;
#pragma unroll
    for (int q = 0; q < 8; q++) {
        int t = tid + 256*q;
        float v0 = (t < Tsz) ? k0[t] : 0.0f;
        float v1 = (t < Tsz) ? k1[t] : 0.0f;
        A[PDC(t)] = make_float2(v0, v1);
    }
    fft2048c(A, Bc, tws);
    float2* K0 = d_kf + (layer*Dsz + d0)*FFTN;
    float2* K1 = d_kf + (layer*Dsz + d1)*FFTN;
#pragma unroll
    for (int q = 0; q < 8; q++) {
        int f = tid + 256*q;
        int fm = (FFTN - f) & (FFTN - 1);
        float2 Zf = A[PDC(f)];
        float2 Zm = A[PDC(fm)];
        K0[f] = make_float2(0.5f*(Zf.x + Zm.x), 0.5f*(Zf.y - Zm.y));
        K1[f] = make_float2(0.5f*(Zf.y + Zm.y), 0.5f*(Zm.x - Zf.x));
    }
}

// ---- input projection + LN + pos-enc + L2-normalize -> d_xt2 (B,D,T) -------
// 128 threads; each owns 2 d's (tid, tid+128) so every x load feeds 2 FMAs.
__global__ void in_proj_ln_kernel(const float* __restrict__ x,
                                  const float* __restrict__ b_in,
                                  const float* __restrict__ g,
                                  const float* __restrict__ bbp) {
    int b = blockIdx.x, t0 = blockIdx.y * 20;
    int tid = threadIdx.x;          // 128
    int lane = tid & 31, w = tid >> 5;   // 4 warps
    int d0 = tid, d1 = tid + 128;
    __shared__ float ws[32][256];
    __shared__ float xs[32][20];
    __shared__ float red1[4][20], red2[4][20];
    __shared__ float msh[20], ish[20];
    float acc0[20], acc1[20];
#pragma unroll
    for (int j = 0; j < 20; j++) { acc0[j] = 0.0f; acc1[j] = 0.0f; }
    for (int c0 = 0; c0 < Csz; c0 += 32) {
        __syncthreads();
        for (int l = tid; l < 32*256; l += 128) {
            int i = l >> 8, col = l & 255;
            ws[i][col] = (c0 + i < Csz) ? d_wt[(c0 + i)*Dsz + col] : 0.0f;
        }
        for (int l = tid; l < 640; l += 128) {
            int cc = l / 20, j = l % 20;
            xs[cc][j] = (c0 + cc < Csz) ? x[(b*Csz + c0 + cc)*Tsz + t0 + j] : 0.0f;
        }
        __syncthreads();
#pragma unroll 4
        for (int cc = 0; cc < 32; cc++) {
            float w0 = ws[cc][d0];
            float w1 = ws[cc][d1];
#pragma unroll
            for (int j = 0; j < 20; j++) {
                float xv = xs[cc][j];
                acc0[j] += w0 * xv;
                acc1[j] += w1 * xv;
            }
        }
    }
    float bias0 = b_in[d0], bias1 = b_in[d1];
#pragma unroll
    for (int j = 0; j < 20; j++) { acc0[j] += bias0; acc1[j] += bias1; }
    // block reduction 1: mean / var per t
#pragma unroll
    for (int j = 0; j < 20; j++) {
        float sv = acc0[j] + acc1[j];
        float sq = acc0[j]*acc0[j] + acc1[j]*acc1[j];
#pragma unroll
        for (int off = 16; off; off >>= 1) {
            sv += __shfl_xor_sync(0xffffffffu, sv, off);
            sq += __shfl_xor_sync(0xffffffffu, sq, off);
        }
        if (lane == 0) { red1[w][j] = sv; red2[w][j] = sq; }
    }
    __syncthreads();
    if (tid < 20) {
        float S = 0.f, Q = 0.f;
        for (int ww = 0; ww < 4; ww++) { S += red1[ww][tid]; Q += red2[ww][tid]; }
        float m = S * (1.0f/256.0f);
        float var = Q * (1.0f/256.0f) - m*m;
        msh[tid] = m; ish[tid] = rsqrtf(var + 1e-5f);
    }
    __syncthreads();
    float g0 = g[d0], g1 = g[d1], bv0 = bbp[d0], bv1 = bbp[d1];
#pragma unroll
    for (int j = 0; j < 20; j++) {
        float m = msh[j], is = ish[j];
        acc0[j] = (acc0[j] - m)*is*g0 + bv0 + d_pe[(t0 + j)*Dsz + d0];
        acc1[j] = (acc1[j] - m)*is*g1 + bv1 + d_pe[(t0 + j)*Dsz + d1];
    }
    // block reduction 2: L2 norm per t
#pragma unroll
    for (int j = 0; j < 20; j++) {
        float sq = acc0[j]*acc0[j] + acc1[j]*acc1[j];
#pragma unroll
        for (int off = 16; off; off >>= 1)
            sq += __shfl_xor_sync(0xffffffffu, sq, off);
        if (lane == 0) red1[w][j] = sq;
    }
    __syncthreads();
    if (tid < 20) {
        float Q = 0.f;
        for (int ww = 0; ww < 4; ww++) Q += red1[ww][tid];
        float nrm = sqrtf(Q) + 1e-8f;
        d_nrm[b*Tsz + t0 + tid] = nrm;
        ish[tid] = 1.0f / nrm;
    }
    __syncthreads();
#pragma unroll
    for (int j = 0; j < 20; j++) { acc0[j] *= ish[j]; acc1[j] *= ish[j]; }
    float4* op0 = reinterpret_cast<float4*>(d_xt2 + ((size_t)b*Dsz + d0)*Tsz + t0);
    float4* op1 = reinterpret_cast<float4*>(d_xt2 + ((size_t)b*Dsz + d1)*Tsz + t0);
#pragma unroll
    for (int q = 0; q < 5; q++) {
        op0[q] = make_float4(acc0[4*q], acc0[4*q+1], acc0[4*q+2], acc0[4*q+3]);
        op1[q] = make_float4(acc1[4*q], acc1[4*q+1], acc1[4*q+2], acc1[4*q+3]);
    }
}

// -------- FFT conv + gate + gelu + residual (z = gelu(y)+1.1h), in-place ----
__global__ void fft_conv_kernel(int layer, const float* __restrict__ s4_D) {
    __shared__ float2 A[CBUF], Bc[CBUF];
    __shared__ float2 tws[280];
    int tid = threadIdx.x;
    int b = blockIdx.x, dp = blockIdx.y;
    int d0 = dp*2, d1 = dp*2 + 1;
    tws[PDC(tid)] = make_float2(d_twr[tid], d_twi[tid]);
    float* x0 = d_xt2 + ((size_t)b*Dsz + d0)*Tsz;
    float* x1 = d_xt2 + ((size_t)b*Dsz + d1)*Tsz;
    const float* np = d_nrm + b*Tsz;
    float xr0[4], xr1[4], nr[4];
#pragma unroll
    for (int q = 0; q < 8; q++) {
        int t = tid + 256*q;
        float v0 = 0.0f, v1 = 0.0f;
        if (t < Tsz) { v0 = x0[t]; v1 = x1[t]; }
        if (q < 4) {
            xr0[q] = v0; xr1[q] = v1;
            nr[q] = (t < Tsz) ? np[t] : 0.0f;
        }
        A[PDC(t)] = make_float2(v0, v1);
    }
    fft2048c(A, Bc, tws);   // Z in A
    const float2* K0 = d_kf + (layer*Dsz + d0)*FFTN;
    const float2* K1 = d_kf + (layer*Dsz + d1)*FFTN;
#pragma unroll
    for (int q = 0; q < 8; q++) {
        int f = tid + 256*q;
        int fm = (FFTN - f) & (FFTN - 1);
        float2 Zf = A[PDC(f)];
        float2 Zm = A[PDC(fm)];
        C2 X0; X0.x = 0.5f*(Zf.x + Zm.x); X0.y = 0.5f*(Zf.y - Zm.y);
        C2 X1; X1.x = 0.5f*(Zf.y + Zm.y); X1.y = 0.5f*(Zm.x - Zf.x);
        float2 k0 = K0[f], k1 = K1[f];
        C2 c0; c0.x = k0.x; c0.y = k0.y;
        C2 c1; c1.x = k1.x; c1.y = k1.y;
        C2 Y0 = cmul(X0, c0);
        C2 Y1 = cmul(X1, c1);
        // conj(S), S = Y0 + i*Y1
        Bc[PDC(f)] = make_float2(Y0.x - Y1.y, -(Y0.y + Y1.x));
    }
    fft2048c(Bc, A, tws);   // V in Bc; ifft = conj(V)/N
    float gate0 = 1.0f / (1.0f + expf(-s4_D[layer*Dsz + d0]));
    float gate1 = 1.0f / (1.0f + expf(-s4_D[layer*Dsz + d1]));
    const float inv = 1.0f / (float)FFTN;
#pragma unroll
    for (int q = 0; q < 4; q++) {
        int t = tid + 256*q;
        if (t < Tsz) {
            float2 V = Bc[PDC(t)];
            float y0 =  V.x*inv + xr0[q]*gate0;
            float y1 = -V.y*inv + xr1[q]*gate1;
            float gl0 = 0.5f*y0*(1.0f + erff(y0*0.70710678118654752f));
            float gl1 = 0.5f*y1*(1.0f + erff(y1*0.70710678118654752f));
            x0[t] = gl0 + 1.1f*xr0[q]*nr[q];   // z = gelu(y) + 1.1*h
            x1[t] = gl1 + 1.1f*xr1[q]*nr[q];
        }
    }
}

// ---- post: LN(z); last -> d_h (B,T,D); else normalized transposed + norms --
__global__ void post_ln_norm_t_kernel(int layer, int last,
                                      const float* __restrict__ ln_g,
                                      const float* __restrict__ ln_b) {
    __shared__ float tile[32][257];
    int b = blockIdx.x, t0 = blockIdx.y * 32;
    int tid = threadIdx.x, lane = tid & 31, w = tid >> 5;
#pragma unroll
    for (int i = 0; i < 32; i++) {
        int dd = i*8 + w;
        int t = t0 + lane;
        tile[lane][dd] = (t < Tsz) ? d_xt2[((size_t)b*Dsz + dd)*Tsz + t] : 0.0f;
    }
    __syncthreads();
    const float* g  = ln_g + layer*Dsz;
    const float* bb = ln_b + layer*Dsz;
#pragma unroll
    for (int j = 0; j < 4; j++) {
        int r = w + 8*j;
        int t = t0 + r;
        if (t >= Tsz) continue;
        float z[8]; float s = 0.f, s2 = 0.f;
#pragma unroll
        for (int k = 0; k < 8; k++) {
            float zz = tile[r][lane + 32*k];
            z[k] = zz; s += zz; s2 += zz*zz;
        }
#pragma unroll
        for (int off = 16; off; off >>= 1) {
            s  += __shfl_xor_sync(0xffffffffu, s,  off);
            s2 += __shfl_xor_sync(0xffffffffu, s2, off);
        }
        float m = s * (1.0f/256.0f);
        float var = s2 * (1.0f/256.0f) - m*m;
        float is = rsqrtf(var + 1e-5f);
        if (last) {
            float* hp = d_h + ((size_t)b*Tsz + t)*Dsz;
#pragma unroll
            for (int k = 0; k < 8; k++) {
                int dd = lane + 32*k;
                hp[dd] = (z[k] - m)*is*g[dd] + bb[dd];
            }
        } else {
            float o[8]; float ss = 0.f;
#pragma unroll
            for (int k = 0; k < 8; k++) {
                int dd = lane + 32*k;
                float ov = (z[k] - m)*is*g[dd] + bb[dd];
                o[k] = ov; ss += ov*ov;
            }
#pragma unroll
            for (int off = 16; off; off >>= 1) ss += __shfl_xor_sync(0xffffffffu, ss, off);
            float nrm = sqrtf(ss) + 1e-8f;
            float invn = 1.0f / nrm;
            if (lane == 0) d_nrm[b*Tsz + t] = nrm;
#pragma unroll
            for (int k = 0; k < 8; k++) tile[r][lane + 32*k] = o[k]*invn;
        }
    }
    if (last) return;
    __syncthreads();
#pragma unroll
    for (int i = 0; i < 32; i++) {
        int dd = i*8 + w;
        int t = t0 + lane;
        if (t < Tsz) d_xt2[((size_t)b*Dsz + dd)*Tsz + t] = tile[lane][dd];
    }
}

// ---------------- fused MHA pooling + head ----------------
__global__ void pool_head_kernel(const float* __restrict__ cls,
                                 const float* __restrict__ in_w,
                                 const float* __restrict__ in_b,
                                 const float* __restrict__ out_w,
                                 const float* __restrict__ out_b,
                                 const float* __restrict__ hw1,
                                 const float* __restrict__ hb1,
                                 const float* __restrict__ hw2,
                                 const float* __restrict__ hb2,
                                 float* __restrict__ out) {
    int b = blockIdx.x;
    int tid = threadIdx.x, lane = tid & 31, w = tid >> 5;
    __shared__ float Q[256];
    __shared__ float vp[8][256];
    __shared__ float sc[8][1001];
    __shared__ float ch[8];
    __shared__ float red[256];
    __shared__ float hsm[128];

    {
        float acc = in_b[tid];
        for (int c = 0; c < 256; c++) acc += cls[c] * in_w[tid*256 + c];
        Q[tid] = acc;
    }
    __syncthreads();
#pragma unroll
    for (int h = 0; h < 8; h++) {
        float acc = 0.f;
#pragma unroll
        for (int i = 0; i < 32; i++)
            acc += in_w[(256 + h*32 + i)*256 + tid] * Q[h*32 + i];
        vp[h][tid] = acc;
    }
    if (tid < 8) {
        float acc = 0.f;
        for (int i = 0; i < 32; i++) acc += in_b[256 + tid*32 + i] * Q[tid*32 + i];
        ch[tid] = acc;
    }
    __syncthreads();
    const float iss = 0.17677669529663687f; // 1/sqrt(32)
    for (int s = w; s < 1001; s += 8) {
        const float* kvr = (s == 0) ? cls : (d_h + ((size_t)b*Tsz + s - 1)*Dsz);
        float xv[8];
#pragma unroll
        for (int k = 0; k < 8; k++) xv[k] = kvr[lane*8 + k];
#pragma unroll
        for (int h = 0; h < 8; h++) {
            float a = 0.f;
#pragma unroll
            for (int k = 0; k < 8; k++) a += xv[k] * vp[h][lane*8 + k];
#pragma unroll
            for (int off = 16; off; off >>= 1) a += __shfl_xor_sync(0xffffffffu, a, off);
            if (lane == h) sc[h][s] = (a + ch[h]) * iss;
        }
    }
    __syncthreads();
    {
        int h = w;
        float mx = -1e30f;
        for (int s = lane; s < 1001; s += 32) mx = fmaxf(mx, sc[h][s]);
#pragma unroll
        for (int off = 16; off; off >>= 1) mx = fmaxf(mx, __shfl_xor_sync(0xffffffffu, mx, off));
        float sum = 0.f;
        for (int s = lane; s < 1001; s += 32) { float e = expf(sc[h][s] - mx); sc[h][s] = e; sum += e; }
#pragma unroll
        for (int off = 16; off; off >>= 1) sum += __shfl_xor_sync(0xffffffffu, sum, off);
        float invs = 1.0f / sum;
        for (int s = lane; s < 1001; s += 32) sc[h][s] *= invs;
    }
    __syncthreads();
    float pj[8];
#pragma unroll
    for (int h = 0; h < 8; h++) pj[h] = 0.f;
    for (int s = 0; s < 1001; s++) {
        float kvv = (s == 0) ? cls[tid] : d_h[((size_t)b*Tsz + s - 1)*Dsz + tid];
#pragma unroll
        for (int h = 0; h < 8; h++) pj[h] += sc[h][s] * kvv;
    }
    __syncthreads();
#pragma unroll
    for (int h = 0; h < 8; h++) vp[h][tid] = pj[h];
    __syncthreads();
    {
        int h = tid >> 5;
        float acc = in_b[512 + tid];
        for (int j = 0; j < 256; j++) acc += in_w[(512 + tid)*256 + j] * vp[h][j];
        Q[tid] = acc;
    }
    __syncthreads();
    {
        float acc = out_b[tid];
        for (int i = 0; i < 256; i++) acc += out_w[tid*256 + i] * Q[i];
        red[tid] = acc;
    }
    __syncthreads();
    if (tid < 128) {
        float acc = hb1[tid];
        for (int i = 0; i < 256; i++) acc += hw1[tid*256 + i] * red[i];
        hsm[tid] = fmaxf(acc, 0.0f);
    }
    __syncthreads();
    if (w == 0) {
        float a = 0.f;
#pragma unroll
        for (int k = 0; k < 4; k++) a += hsm[lane + 32*k] * hw2[lane + 32*k];
#pragma unroll
        for (int off = 16; off; off >>= 1) a += __shfl_xor_sync(0xffffffffu, a, off);
        if (lane == 0) out[b] = a + hb2[0];
    }
}

// ---------------- launch ----------------
extern "C" void kernel_launch(void* const* d_in, const int* in_sizes, int n_in,
                              void* d_out, int out_size) {
    const float* x        = (const float*)d_in[0];
    const float* w_in     = (const float*)d_in[1];
    const float* b_in     = (const float*)d_in[2];
    const float* ln_in_g  = (const float*)d_in[3];
    const float* ln_in_b  = (const float*)d_in[4];
    const float* s4_B     = (const float*)d_in[5];
    const float* s4_C     = (const float*)d_in[6];
    const float* s4_logdt = (const float*)d_in[7];
    const float* s4_D     = (const float*)d_in[8];
    const float* ln_g     = (const float*)d_in[9];
    const float* ln_b     = (const float*)d_in[10];
    const float* cls      = (const float*)d_in[11];
    const float* mha_in_w = (const float*)d_in[12];
    const float* mha_in_b = (const float*)d_in[13];
    const float* mha_out_w= (const float*)d_in[14];
    const float* mha_out_b= (const float*)d_in[15];
    const float* head_w1  = (const float*)d_in[16];
    const float* head_b1  = (const float*)d_in[17];
    const float* head_w2  = (const float*)d_in[18];
    const float* head_b2  = (const float*)d_in[19];
    float* out = (float*)d_out;

    setup_kernel<<<256, 256>>>(w_in);
    compute_Ad_kernel<<<NL, 512>>>(s4_logdt);
    s4_E_kernel<<<NL, 512>>>();
    s4_W_kernel<<<dim3(Dsz, NL), 64>>>(s4_B);
    s4_scan_kernel<<<dim3(Dsz, NL), 64>>>(s4_C);
    fft_k_kernel<<<dim3(Dsz/2, NL), 256>>>();
    in_proj_ln_kernel<<<dim3(Bsz, 50), 128>>>(x, b_in, ln_in_g, ln_in_b);
    for (int layer = 0; layer < NL; layer++) {
        fft_conv_kernel<<<dim3(Bsz, Dsz/2), 256>>>(layer, s4_D);
        post_ln_norm_t_kernel<<<dim3(Bsz, 32), 256>>>(layer, (layer == NL-1) ? 1 : 0, ln_g, ln_b);
    }
    pool_head_kernel<<<Bsz, 256>>>(cls, mha_in_w, mha_in_b, mha_out_w, mha_out_b,
                                   head_w1, head_b1, head_w2, head_b2, out);
}